// round 2
// baseline (speedup 1.0000x reference)
#include <cuda_runtime.h>

#define BATCH 16384
#define NK 100        // TENSOR_DIM
#define KP 104        // padded k
#define D 200         // 2*TENSOR_DIM
#define H1 512        // EMBED_SIZE/2
#define EM 1024       // EMBED_SIZE
#define WD 300        // WORD_DIM

// ---------------- scratch (device globals; no allocation) ----------------
__device__ float g_catT[D * BATCH];            // cat transposed: [i][b]   13.1 MB
__device__ float g_SpT[D * D * KP];            // sym T, [j][i][k]         16.6 MB
__device__ float g_pdWT[WD * NK];              // pd_W transposed [c][k]
__device__ float g_clWT[D * NK];               // cl_W transposed [i][k]
__device__ float g_l1WT[NK * H1];              // l1_W transposed [k][m]
__device__ float g_term1p[4][BATCH * NK];      // 4 j-range partials       26.2 MB
__device__ float g_h[BATCH * H1];              // hidden layer             33.5 MB

__device__ __forceinline__ float lrelu(float x) { return x >= 0.f ? x : 0.1f * x; }

// ---------------- small transposes ----------------
__global__ void k_prep_small(const float* __restrict__ pd_W,
                             const float* __restrict__ cl_W,
                             const float* __restrict__ l1_W) {
    int stride = gridDim.x * blockDim.x;
    int t0 = blockIdx.x * blockDim.x + threadIdx.x;
    for (int l = t0; l < WD * NK; l += stride) {
        int c = l / NK, k = l - c * NK;
        g_pdWT[l] = pd_W[k * WD + c];
    }
    for (int l = t0; l < D * NK; l += stride) {
        int i = l / NK, k = l - i * NK;
        g_clWT[l] = cl_W[k * D + i];
    }
    for (int l = t0; l < NK * H1; l += stride) {
        int k = l / H1, m = l - k * H1;
        g_l1WT[l] = l1_W[m * NK + k];
    }
}

// ---------------- build symmetric-packed T:  Sp[j][i][k] ----------------
// i>j : T[k,i,j] + T[k,j,i];  i==j : T[k,i,i];  i<j or k>=100 : 0
__global__ void k_prep_spt(const float* __restrict__ T) {
    int j = blockIdx.x, i = blockIdx.y;
    int k = threadIdx.x;            // blockDim = 128
    if (k >= KP) return;
    float v = 0.f;
    if (k < NK && i >= j) {
        if (i > j) v = T[(k * D + i) * D + j] + T[(k * D + j) * D + i];
        else       v = T[(k * D + i) * D + i];
    }
    g_SpT[(j * D + i) * KP + k] = v;
}

// ---------------- embedding gather + projdown + leaky ----------------
// rows = slot*B + b (slot-major); CTA handles 16 consecutive rows (same slot)
__global__ void __launch_bounds__(256) k_cat(const int* __restrict__ x,
                                             const float* __restrict__ embed_W,
                                             const float* __restrict__ pd_b) {
    __shared__ float e_s[16][WD + 4];
    __shared__ float o_s[NK][17];
    __shared__ int   xs[16];
    int g = blockIdx.x;                  // 0..2047
    int row0 = g * 16;
    int slot = row0 / BATCH;             // 0 (att) or 1 (obj)
    int bbase = row0 - slot * BATCH;
    int t = threadIdx.x;
    if (t < 16) xs[t] = x[(bbase + t) * 2 + slot];
    __syncthreads();
    for (int l = t; l < 16 * WD; l += 256) {
        int r = l / WD, c = l - r * WD;
        e_s[r][c] = embed_W[(size_t)xs[r] * WD + c];
    }
    __syncthreads();
    int k  = t & 127;
    int rt = t >> 7;
    if (k < NK) {
        float acc[8];
#pragma unroll
        for (int q = 0; q < 8; ++q) acc[q] = 0.f;
        for (int c4 = 0; c4 < WD; c4 += 4) {
            float w0 = g_pdWT[(c4 + 0) * NK + k];
            float w1 = g_pdWT[(c4 + 1) * NK + k];
            float w2 = g_pdWT[(c4 + 2) * NK + k];
            float w3 = g_pdWT[(c4 + 3) * NK + k];
#pragma unroll
            for (int q = 0; q < 8; ++q) {
                float4 e = *(const float4*)&e_s[rt + 2 * q][c4];
                acc[q] += e.x * w0 + e.y * w1 + e.z * w2 + e.w * w3;
            }
        }
        float bk = pd_b[k];
#pragma unroll
        for (int q = 0; q < 8; ++q)
            o_s[k][rt + 2 * q] = lrelu(acc[q] + bk);
    }
    __syncthreads();
    for (int l = t; l < NK * 16; l += 256) {
        int kk = l >> 4, col = l & 15;
        g_catT[(slot * NK + kk) * BATCH + bbase + col] = o_s[kk][col];
    }
}

// ---------------- main kernel: triangular trilinear form ----------------
// CTA tile: 64 b  x  104 k (100 real).  threads = 16(b) x 26(k) = 416.
// blockIdx.y selects a j-range (equal-work quarters of the triangle).
__global__ void __launch_bounds__(416) k_main() {
    extern __shared__ float cat_s[];     // [D][64]
    int t  = threadIdx.x;
    int bt = t & 15;                     // 0..15 -> 4 b each
    int kt = t >> 4;                     // 0..25 -> 4 k each
    int b0 = blockIdx.x * 64;
    for (int l = t; l < D * 64; l += 416)
        cat_s[l] = g_catT[(l >> 6) * BATCH + b0 + (l & 63)];
    __syncthreads();

    int y = blockIdx.y;
    int jlo = (y == 0) ? 0  : (y == 1) ? 27 : (y == 2) ? 59  : 100;
    int jhi = (y == 0) ? 27 : (y == 1) ? 59 : (y == 2) ? 100 : 200;

    float acc[4][4];
#pragma unroll
    for (int r = 0; r < 4; ++r)
#pragma unroll
        for (int c = 0; c < 4; ++c) acc[r][c] = 0.f;

    for (int j = jlo; j < jhi; ++j) {
        float4 cj = *(const float4*)&cat_s[j * 64 + bt * 4];
        const float4* trow = (const float4*)(g_SpT + (size_t)j * D * KP) + kt;
        float p[4][4];
#pragma unroll
        for (int r = 0; r < 4; ++r)
#pragma unroll
            for (int c = 0; c < 4; ++c) p[r][c] = 0.f;

#pragma unroll 2
        for (int i = j; i < D; ++i) {
            float4 tv = __ldg(trow + i * (KP / 4));
            float4 ca = *(const float4*)&cat_s[i * 64 + bt * 4];
            p[0][0] += ca.x * tv.x; p[0][1] += ca.x * tv.y; p[0][2] += ca.x * tv.z; p[0][3] += ca.x * tv.w;
            p[1][0] += ca.y * tv.x; p[1][1] += ca.y * tv.y; p[1][2] += ca.y * tv.z; p[1][3] += ca.y * tv.w;
            p[2][0] += ca.z * tv.x; p[2][1] += ca.z * tv.y; p[2][2] += ca.z * tv.z; p[2][3] += ca.z * tv.w;
            p[3][0] += ca.w * tv.x; p[3][1] += ca.w * tv.y; p[3][2] += ca.w * tv.z; p[3][3] += ca.w * tv.w;
        }
#pragma unroll
        for (int c = 0; c < 4; ++c) {
            acc[0][c] += p[0][c] * cj.x;
            acc[1][c] += p[1][c] * cj.y;
            acc[2][c] += p[2][c] * cj.z;
            acc[3][c] += p[3][c] * cj.w;
        }
    }
    if (kt < 25) {
        float* dst = g_term1p[y];
#pragma unroll
        for (int r = 0; r < 4; ++r) {
            int b = b0 + bt * 4 + r;
            *(float4*)&dst[b * NK + kt * 4] =
                make_float4(acc[r][0], acc[r][1], acc[r][2], acc[r][3]);
        }
    }
}

// ---------------- term2 + comp + l1 (fused) ----------------
__global__ void __launch_bounds__(256) k_comp(const float* __restrict__ cl_b,
                                              const float* __restrict__ l1_b) {
    __shared__ float cat_s[D][32];
    __shared__ float comp_s[32][KP];
    int b0 = blockIdx.x * 32;
    int t = threadIdx.x;
    for (int l = t; l < D * 32; l += 256)
        cat_s[l >> 5][l & 31] = g_catT[(l >> 5) * BATCH + b0 + (l & 31)];
    __syncthreads();

    // step 1: comp = lrelu(term1 + cat @ cl_W^T + cl_b)
    int k = t & 127, bh = t >> 7;
    if (k < NK) {
        float acc[16];
#pragma unroll
        for (int q = 0; q < 16; ++q) acc[q] = 0.f;
        for (int i = 0; i < D; ++i) {
            float w = g_clWT[i * NK + k];
#pragma unroll
            for (int q = 0; q < 16; ++q) acc[q] += cat_s[i][bh * 16 + q] * w;
        }
        float cb = cl_b[k];
#pragma unroll
        for (int q = 0; q < 16; ++q) {
            int b = b0 + bh * 16 + q;
            float t1 = g_term1p[0][b * NK + k] + g_term1p[1][b * NK + k] +
                       g_term1p[2][b * NK + k] + g_term1p[3][b * NK + k];
            comp_s[bh * 16 + q][k] = lrelu(t1 + acc[q] + cb);
        }
    }
    __syncthreads();

    // step 2: h = lrelu(comp @ l1_W^T + l1_b)   (each thread: 2 m's x 32 b's)
    int m0 = t;
    float a2[32][2];
#pragma unroll
    for (int bl = 0; bl < 32; ++bl) { a2[bl][0] = 0.f; a2[bl][1] = 0.f; }
    for (int kk = 0; kk < NK; ++kk) {
        float w0 = g_l1WT[kk * H1 + m0];
        float w1 = g_l1WT[kk * H1 + m0 + 256];
#pragma unroll
        for (int bl = 0; bl < 32; ++bl) {
            float cv = comp_s[bl][kk];
            a2[bl][0] += cv * w0;
            a2[bl][1] += cv * w1;
        }
    }
    float bb0 = l1_b[m0], bb1 = l1_b[m0 + 256];
#pragma unroll
    for (int bl = 0; bl < 32; ++bl) {
        g_h[(size_t)(b0 + bl) * H1 + m0]       = lrelu(a2[bl][0] + bb0);
        g_h[(size_t)(b0 + bl) * H1 + m0 + 256] = lrelu(a2[bl][1] + bb1);
    }
}

// ---------------- l2 GEMM: out = h @ l2_W^T + l2_b ----------------
// CTA tile 64b x 128e, threads 16x16, thread 4b x 8e
__global__ void __launch_bounds__(256) k_l2(const float* __restrict__ l2_W,
                                            const float* __restrict__ l2_b,
                                            float* __restrict__ out) {
    __shared__ float hs[32][65];
    __shared__ float ws[32][129];
    int b0 = blockIdx.x * 64, e0 = blockIdx.y * 128;
    int t = threadIdx.x;
    int bt = t & 15, et = t >> 4;
    float acc[4][8];
#pragma unroll
    for (int r = 0; r < 4; ++r)
#pragma unroll
        for (int c = 0; c < 8; ++c) acc[r][c] = 0.f;

    for (int k0 = 0; k0 < H1; k0 += 32) {
        for (int l = t; l < 2048; l += 256) {
            int r = l >> 5, c = l & 31;
            hs[c][r] = g_h[(size_t)(b0 + r) * H1 + k0 + c];
        }
        for (int l = t; l < 4096; l += 256) {
            int r = l >> 5, c = l & 31;
            ws[c][r] = l2_W[(size_t)(e0 + r) * H1 + k0 + c];
        }
        __syncthreads();
#pragma unroll
        for (int kc = 0; kc < 32; ++kc) {
            float h0 = hs[kc][bt * 4 + 0];
            float h1 = hs[kc][bt * 4 + 1];
            float h2 = hs[kc][bt * 4 + 2];
            float h3 = hs[kc][bt * 4 + 3];
#pragma unroll
            for (int c = 0; c < 8; ++c) {
                float w = ws[kc][et * 8 + c];
                acc[0][c] += h0 * w;
                acc[1][c] += h1 * w;
                acc[2][c] += h2 * w;
                acc[3][c] += h3 * w;
            }
        }
        __syncthreads();
    }
    float bias[8];
#pragma unroll
    for (int c = 0; c < 8; ++c) bias[c] = l2_b[e0 + et * 8 + c];
#pragma unroll
    for (int r = 0; r < 4; ++r) {
        size_t base = (size_t)(b0 + bt * 4 + r) * EM + e0 + et * 8;
#pragma unroll
        for (int c = 0; c < 8; ++c) out[base + c] = acc[r][c] + bias[c];
    }
}

// ---------------- row-wise L2 normalization (in place) ----------------
__global__ void __launch_bounds__(256) k_norm(float* __restrict__ out) {
    __shared__ float wsum[8];
    int b = blockIdx.x;
    int t = threadIdx.x;
    float4* row = (float4*)(out + (size_t)b * EM);
    float4 v = row[t];
    float s = v.x * v.x + v.y * v.y + v.z * v.z + v.w * v.w;
#pragma unroll
    for (int off = 16; off > 0; off >>= 1)
        s += __shfl_xor_sync(0xffffffffu, s, off);
    if ((t & 31) == 0) wsum[t >> 5] = s;
    __syncthreads();
    float tot = wsum[0] + wsum[1] + wsum[2] + wsum[3] +
                wsum[4] + wsum[5] + wsum[6] + wsum[7];
    float inv = rsqrtf(tot);
    row[t] = make_float4(v.x * inv, v.y * inv, v.z * inv, v.w * inv);
}

// ---------------- launch ----------------
extern "C" void kernel_launch(void* const* d_in, const int* in_sizes, int n_in,
                              void* d_out, int out_size) {
    const int*   x       = (const int*)d_in[0];
    const float* embed_W = (const float*)d_in[2];
    const float* pd_W    = (const float*)d_in[3];
    const float* pd_b    = (const float*)d_in[4];
    const float* comp_T  = (const float*)d_in[5];
    const float* cl_W    = (const float*)d_in[6];
    const float* cl_b    = (const float*)d_in[7];
    const float* l1_W    = (const float*)d_in[8];
    const float* l1_b    = (const float*)d_in[9];
    const float* l2_W    = (const float*)d_in[10];
    const float* l2_b    = (const float*)d_in[11];
    float* out = (float*)d_out;

    k_prep_small<<<128, 256>>>(pd_W, cl_W, l1_W);
    k_prep_spt<<<dim3(D, D), 128>>>(comp_T);
    k_cat<<<(2 * BATCH) / 16, 256>>>(x, embed_W, pd_b);

    cudaFuncSetAttribute(k_main, cudaFuncAttributeMaxDynamicSharedMemorySize,
                         D * 64 * sizeof(float));
    k_main<<<dim3(BATCH / 64, 4), 416, D * 64 * sizeof(float)>>>();

    k_comp<<<BATCH / 32, 256>>>(cl_b, l1_b);
    k_l2<<<dim3(BATCH / 64, EM / 128), 256>>>(l2_W, l2_b, out);
    k_norm<<<BATCH, 256>>>(out);
}

// round 4
// speedup vs baseline: 3.4225x; 3.4225x over previous
#include <cuda_runtime.h>
#include <cstdint>

#define BATCH 16384
#define NK 100        // TENSOR_DIM
#define D 200         // 2*TENSOR_DIM
#define H1 512        // EMBED_SIZE/2
#define EM 1024       // EMBED_SIZE
#define WD 300        // WORD_DIM

#define PREAL 20400   // real pair count (padded runs)
#define PPAD  20416   // padded to 32
#define NGROUP 5104   // PPAD / 4
#define NC32 638      // PPAD / 32

// ---------------- scratch (device globals; no allocation) ----------------
__device__ float g_catT[D * BATCH];            // cat transposed [i][b]
__device__ float g_SpB[PPAD * 120];            // Sp tf32, row-major [p][n(120)]  9.8MB
__device__ int2  g_groups[NGROUP];             // (j, i0) per 4-pair group
__device__ float g_pdWT[WD * NK];
__device__ float g_clWT[D * NK];
__device__ float g_l1WT[NK * H1];
__device__ float g_l2Wt[H1 * EM];              // l2_W transposed [k][e], tf32 bits
__device__ float g_term1[BATCH * NK];
__device__ float g_h[BATCH * H1];              // tf32 bits

__device__ __forceinline__ float lrelu(float x) { return x >= 0.f ? x : 0.1f * x; }

__device__ __forceinline__ uint32_t smem_u32(const void* p) {
    return (uint32_t)__cvta_generic_to_shared(p);
}
__device__ __forceinline__ uint32_t f2tf32(float x) {
    uint32_t r; asm("cvt.rna.tf32.f32 %0, %1;" : "=r"(r) : "f"(x)); return r;
}
#define CP_ASYNC16(dst, src) \
    asm volatile("cp.async.cg.shared.global [%0], [%1], 16;" :: "r"(dst), "l"(src) : "memory")
#define CP_COMMIT() asm volatile("cp.async.commit_group;" ::: "memory")

__device__ __forceinline__ void mma_tf32(float* d, const uint32_t* a,
                                         uint32_t b0, uint32_t b1) {
    asm volatile(
        "mma.sync.aligned.m16n8k8.row.col.f32.tf32.tf32.f32 "
        "{%0,%1,%2,%3}, {%4,%5,%6,%7}, {%8,%9}, {%0,%1,%2,%3};"
        : "+f"(d[0]), "+f"(d[1]), "+f"(d[2]), "+f"(d[3])
        : "r"(a[0]), "r"(a[1]), "r"(a[2]), "r"(a[3]), "r"(b0), "r"(b1));
}

// ---------------- prep: small transposes ----------------
__global__ void k_prep_small(const float* __restrict__ pd_W,
                             const float* __restrict__ cl_W,
                             const float* __restrict__ l1_W) {
    int stride = gridDim.x * blockDim.x;
    int t0 = blockIdx.x * blockDim.x + threadIdx.x;
    for (int l = t0; l < WD * NK; l += stride) {
        int c = l / NK, k = l - c * NK;
        g_pdWT[l] = pd_W[k * WD + c];
    }
    for (int l = t0; l < D * NK; l += stride) {
        int i = l / NK, k = l - i * NK;
        g_clWT[l] = cl_W[k * D + i];
    }
    for (int l = t0; l < NK * H1; l += stride) {
        int k = l / H1, m = l - k * H1;
        g_l1WT[l] = l1_W[m * NK + k];
    }
}

__global__ void k_prep_l2w(const float* __restrict__ l2_W) {
    int idx = blockIdx.x * 256 + threadIdx.x;       // k*1024 + e
    int k = idx >> 10, e = idx & 1023;
    g_l2Wt[idx] = __uint_as_float(f2tf32(l2_W[e * H1 + k]));
}

// ---------------- prep: pair-group table ----------------
// pairs ordered: for j=0..199, i from (j & ~3) to 199 (runs multiple of 4)
__global__ void k_prep_groups() {
    int j = threadIdx.x;
    if (j < 200) {
        int q = j >> 2, r = j & 3;
        int S = 2 * q * (q - 1) + r * q;
        int gbase = 50 * j - S;
        int i0 = j & ~3;
        int ng = (200 - i0) >> 2;
        for (int g = 0; g < ng; ++g)
            g_groups[gbase + g] = make_int2(j, i0 + 4 * g);
    }
    if (j >= 200 && j < 204)
        g_groups[5100 + (j - 200)] = make_int2(0, 0);
}

// ---------------- prep: Sp rows (pairs) x 120 n-cols, tf32 ----------------
__global__ void __launch_bounds__(256) k_prep_spb(const float* __restrict__ T) {
    int c = blockIdx.x;              // 638 chunks of 32 pairs
    for (int e = threadIdx.x; e < 3840; e += 256) {
        int l = e / 120, n = e - l * 120;
        int p = c * 32 + l;
        float v = 0.f;
        if (n < NK && p < PREAL) {
            int2 gi = g_groups[p >> 2];
            int i = gi.y + (p & 3), j = gi.x;
            if (i > j)       v = T[(n * D + i) * D + j] + T[(n * D + j) * D + i];
            else if (i == j) v = T[(n * D + i) * D + i];
        }
        g_SpB[(size_t)p * 120 + n] = __uint_as_float(f2tf32(v));
    }
}

// ---------------- embedding gather + projdown + leaky ----------------
__global__ void __launch_bounds__(256) k_cat(const int* __restrict__ x,
                                             const float* __restrict__ embed_W,
                                             const float* __restrict__ pd_b) {
    __shared__ float e_s[16][WD + 4];
    __shared__ float o_s[NK][17];
    __shared__ int   xs[16];
    int g = blockIdx.x;
    int row0 = g * 16;
    int slot = row0 / BATCH;
    int bbase = row0 - slot * BATCH;
    int t = threadIdx.x;
    if (t < 16) xs[t] = x[(bbase + t) * 2 + slot];
    __syncthreads();
    for (int l = t; l < 16 * WD; l += 256) {
        int r = l / WD, c = l - r * WD;
        e_s[r][c] = embed_W[(size_t)xs[r] * WD + c];
    }
    __syncthreads();
    int k  = t & 127;
    int rt = t >> 7;
    if (k < NK) {
        float acc[8];
#pragma unroll
        for (int q = 0; q < 8; ++q) acc[q] = 0.f;
        for (int c4 = 0; c4 < WD; c4 += 4) {
            float w0 = g_pdWT[(c4 + 0) * NK + k];
            float w1 = g_pdWT[(c4 + 1) * NK + k];
            float w2 = g_pdWT[(c4 + 2) * NK + k];
            float w3 = g_pdWT[(c4 + 3) * NK + k];
#pragma unroll
            for (int q = 0; q < 8; ++q) {
                float4 e = *(const float4*)&e_s[rt + 2 * q][c4];
                acc[q] += e.x * w0 + e.y * w1 + e.z * w2 + e.w * w3;
            }
        }
        float bk = pd_b[k];
#pragma unroll
        for (int q = 0; q < 8; ++q)
            o_s[k][rt + 2 * q] = lrelu(acc[q] + bk);
    }
    __syncthreads();
    for (int l = t; l < NK * 16; l += 256) {
        int kk = l >> 4, col = l & 15;
        g_catT[(slot * NK + kk) * BATCH + bbase + col] = o_s[kk][col];
    }
}

// ---------------- main: term1 via mma.sync tf32 ----------------
// CTA: 128 b x 112 n. 8 warps = 4 row-groups(32b) x 2 col-groups(56n).
// K loop: 638 chunks of 32 pairs, cp.async double-buffered.
#define CAT_STRIDE 228            // words; 228 % 32 == 4 -> conflict-free A frags
#define SP_OFF   116736           // 128 * 228 * 4
#define SP_BYTES 15360            // 32 * 120 * 4
#define GRP_OFF  147456           // SP_OFF + 2*SP_BYTES
#define SMEM_MAIN 188288          // GRP_OFF + 5104*8

__global__ void __launch_bounds__(256, 1) k_main_mma() {
    extern __shared__ char smem[];
    float* cat = (float*)smem;
    int2*  grp = (int2*)(smem + GRP_OFF);
    uint32_t sb = smem_u32(smem);
    int tid = threadIdx.x, lane = tid & 31, wid = tid >> 5;
    int b0 = blockIdx.x * 128;

    // prologue: kick off chunk 0 load first
    {
        const char* src = (const char*)g_SpB;
        for (int i = tid; i < 960; i += 256)
            CP_ASYNC16(sb + SP_OFF + i * 16, src + i * 16);
        CP_COMMIT();
    }
    for (int l = tid; l < NGROUP; l += 256) grp[l] = g_groups[l];
    for (int l = tid; l < D * 128; l += 256) {
        int i = l >> 7, b = l & 127;
        cat[b * CAT_STRIDE + i] = g_catT[i * BATCH + b0 + b];
    }

    int rw = wid & 3, cw = wid >> 2;
    int R0 = rw * 32;
    int rA = R0 + (lane >> 2);
    int ic = lane & 3;
    int nb = cw * 56 + (lane >> 2);

    float acc[2][7][4];
#pragma unroll
    for (int f = 0; f < 2; ++f)
#pragma unroll
        for (int t = 0; t < 7; ++t)
#pragma unroll
            for (int q = 0; q < 4; ++q) acc[f][t][q] = 0.f;

    __syncthreads();   // cat + grp ready

    for (int c = 0; c < NC32; ++c) {
        int s = c & 1;
        if (c + 1 < NC32) {
            const char* src = (const char*)g_SpB + (size_t)(c + 1) * SP_BYTES;
            uint32_t dst = sb + SP_OFF + (s ^ 1) * SP_BYTES;
            for (int i = tid; i < 960; i += 256)
                CP_ASYNC16(dst + i * 16, src + i * 16);
            CP_COMMIT();
            asm volatile("cp.async.wait_group 1;" ::: "memory");
        } else {
            asm volatile("cp.async.wait_group 0;" ::: "memory");
        }
        __syncthreads();

        const uint32_t* spu = (const uint32_t*)(smem + SP_OFF + s * SP_BYTES);
        int gb = c * 8;
#pragma unroll
        for (int kk = 0; kk < 4; ++kk) {
            int2 G0 = grp[gb + kk * 2];
            int2 G1 = grp[gb + kk * 2 + 1];
            uint32_t afr[2][4];
#pragma unroll
            for (int f = 0; f < 2; ++f) {
                const float* r0p = cat + (rA + f * 16) * CAT_STRIDE;
                const float* r1p = r0p + 8 * CAT_STRIDE;
                float i0a = r0p[G0.y + ic], j0a = r0p[G0.x];
                float i0b = r1p[G0.y + ic], j0b = r1p[G0.x];
                float i1a = r0p[G1.y + ic], j1a = r0p[G1.x];
                float i1b = r1p[G1.y + ic], j1b = r1p[G1.x];
                afr[f][0] = f2tf32(i0a * j0a);
                afr[f][1] = f2tf32(i0b * j0b);
                afr[f][2] = f2tf32(i1a * j1a);
                afr[f][3] = f2tf32(i1b * j1b);
            }
            int krow0 = (kk * 8 + ic) * 120;
            int krow1 = krow0 + 4 * 120;
#pragma unroll
            for (int t = 0; t < 7; ++t) {
                uint32_t bb0 = spu[krow0 + nb + t * 8];
                uint32_t bb1 = spu[krow1 + nb + t * 8];
                mma_tf32(acc[0][t], afr[0], bb0, bb1);
                mma_tf32(acc[1][t], afr[1], bb0, bb1);
            }
        }
        __syncthreads();
    }

    // epilogue: write term1 (cols < 100)
    int cb = cw * 56 + 2 * ic;
#pragma unroll
    for (int f = 0; f < 2; ++f) {
        int r = b0 + R0 + f * 16 + (lane >> 2);
#pragma unroll
        for (int t = 0; t < 7; ++t) {
            int n0 = cb + t * 8;
            if (n0 < NK) {
                *(float2*)&g_term1[(size_t)r * NK + n0] =
                    make_float2(acc[f][t][0], acc[f][t][1]);
                *(float2*)&g_term1[(size_t)(r + 8) * NK + n0] =
                    make_float2(acc[f][t][2], acc[f][t][3]);
            }
        }
    }
}

// ---------------- term2 + comp + l1 (fused); h stored as tf32 bits ----------------
__global__ void __launch_bounds__(256) k_comp(const float* __restrict__ cl_b,
                                              const float* __restrict__ l1_b) {
    __shared__ float cat_s[D][32];
    __shared__ float comp_s[32][104];
    int b0 = blockIdx.x * 32;
    int t = threadIdx.x;
    for (int l = t; l < D * 32; l += 256)
        cat_s[l >> 5][l & 31] = g_catT[(l >> 5) * BATCH + b0 + (l & 31)];
    __syncthreads();

    int k = t & 127, bh = t >> 7;
    if (k < NK) {
        float acc[16];
#pragma unroll
        for (int q = 0; q < 16; ++q) acc[q] = 0.f;
        for (int i = 0; i < D; ++i) {
            float w = g_clWT[i * NK + k];
#pragma unroll
            for (int q = 0; q < 16; ++q) acc[q] += cat_s[i][bh * 16 + q] * w;
        }
        float cb = cl_b[k];
#pragma unroll
        for (int q = 0; q < 16; ++q) {
            int b = b0 + bh * 16 + q;
            float t1 = g_term1[(size_t)b * NK + k];
            comp_s[bh * 16 + q][k] = lrelu(t1 + acc[q] + cb);
        }
    }
    __syncthreads();

    int m0 = t;
    float a2[32][2];
#pragma unroll
    for (int bl = 0; bl < 32; ++bl) { a2[bl][0] = 0.f; a2[bl][1] = 0.f; }
    for (int kk = 0; kk < NK; ++kk) {
        float w0 = g_l1WT[kk * H1 + m0];
        float w1 = g_l1WT[kk * H1 + m0 + 256];
#pragma unroll
        for (int bl = 0; bl < 32; ++bl) {
            float cv = comp_s[bl][kk];
            a2[bl][0] += cv * w0;
            a2[bl][1] += cv * w1;
        }
    }
    float bb0 = l1_b[m0], bb1 = l1_b[m0 + 256];
#pragma unroll
    for (int bl = 0; bl < 32; ++bl) {
        g_h[(size_t)(b0 + bl) * H1 + m0] =
            __uint_as_float(f2tf32(lrelu(a2[bl][0] + bb0)));
        g_h[(size_t)(b0 + bl) * H1 + m0 + 256] =
            __uint_as_float(f2tf32(lrelu(a2[bl][1] + bb1)));
    }
}

// ---------------- l2 GEMM via mma.sync tf32 ----------------
// CTA 128b x 128e; 8 warps = 4 row-groups x 2 col-groups (64e = 8 n-tiles)
__global__ void __launch_bounds__(256) k_l2_mma(const float* __restrict__ l2_b,
                                                float* __restrict__ out) {
    __shared__ uint32_t hs[2][128 * 20];
    __shared__ uint32_t ws[2][16 * 136];
    int tid = threadIdx.x, lane = tid & 31, wid = tid >> 5;
    int b0 = blockIdx.x * 128, e0 = blockIdx.y * 128;
    int rw = wid & 3, cw = wid >> 2;
    int R0 = rw * 32;
    int ic = lane & 3;

    float acc[2][8][4];
#pragma unroll
    for (int f = 0; f < 2; ++f)
#pragma unroll
        for (int t = 0; t < 8; ++t)
#pragma unroll
            for (int q = 0; q < 4; ++q) acc[f][t][q] = 0.f;

    auto issue = [&](int kt, int s) {
        for (int i = tid; i < 512; i += 256) {
            int r = i >> 2, q = i & 3;
            const char* src = (const char*)(g_h + (size_t)(b0 + r) * H1 + kt * 16) + q * 16;
            CP_ASYNC16(smem_u32(&hs[s][r * 20]) + q * 16, src);
        }
        for (int i = tid; i < 512; i += 256) {
            int r = i >> 5, q = i & 31;
            const char* src = (const char*)(g_l2Wt + (size_t)(kt * 16 + r) * EM + e0) + q * 16;
            CP_ASYNC16(smem_u32(&ws[s][r * 136]) + q * 16, src);
        }
        CP_COMMIT();
    };
    issue(0, 0);

    for (int kt = 0; kt < 32; ++kt) {
        int s = kt & 1;
        if (kt + 1 < 32) {
            issue(kt + 1, s ^ 1);
            asm volatile("cp.async.wait_group 1;" ::: "memory");
        } else {
            asm volatile("cp.async.wait_group 0;" ::: "memory");
        }
        __syncthreads();
#pragma unroll
        for (int kk = 0; kk < 2; ++kk) {
            uint32_t af[2][4];
#pragma unroll
            for (int f = 0; f < 2; ++f) {
                const uint32_t* hp =
                    &hs[s][(R0 + f * 16 + (lane >> 2)) * 20 + kk * 8 + ic];
                af[f][0] = hp[0];
                af[f][1] = hp[8 * 20];
                af[f][2] = hp[4];
                af[f][3] = hp[8 * 20 + 4];
            }
            const uint32_t* wp = &ws[s][(kk * 8 + ic) * 136 + cw * 64 + (lane >> 2)];
#pragma unroll
            for (int t = 0; t < 8; ++t) {
                uint32_t bb0 = wp[t * 8];
                uint32_t bb1 = wp[4 * 136 + t * 8];
                mma_tf32(acc[0][t], af[0], bb0, bb1);
                mma_tf32(acc[1][t], af[1], bb0, bb1);
            }
        }
        __syncthreads();
    }

#pragma unroll
    for (int t = 0; t < 8; ++t) {
        int e = e0 + cw * 64 + t * 8 + 2 * ic;
        float be0 = l2_b[e], be1 = l2_b[e + 1];
#pragma unroll
        for (int f = 0; f < 2; ++f) {
            int r = b0 + R0 + f * 16 + (lane >> 2);
            *(float2*)&out[(size_t)r * EM + e] =
                make_float2(acc[f][t][0] + be0, acc[f][t][1] + be1);
            *(float2*)&out[(size_t)(r + 8) * EM + e] =
                make_float2(acc[f][t][2] + be0, acc[f][t][3] + be1);
        }
    }
}

// ---------------- row-wise L2 normalization ----------------
__global__ void __launch_bounds__(256) k_norm(float* __restrict__ out) {
    __shared__ float wsum[8];
    int b = blockIdx.x;
    int t = threadIdx.x;
    float4* row = (float4*)(out + (size_t)b * EM);
    float4 v = row[t];
    float s = v.x * v.x + v.y * v.y + v.z * v.z + v.w * v.w;
#pragma unroll
    for (int off = 16; off > 0; off >>= 1)
        s += __shfl_xor_sync(0xffffffffu, s, off);
    if ((t & 31) == 0) wsum[t >> 5] = s;
    __syncthreads();
    float tot = wsum[0] + wsum[1] + wsum[2] + wsum[3] +
                wsum[4] + wsum[5] + wsum[6] + wsum[7];
    float inv = rsqrtf(tot);
    row[t] = make_float4(v.x * inv, v.y * inv, v.z * inv, v.w * inv);
}

// ---------------- launch ----------------
extern "C" void kernel_launch(void* const* d_in, const int* in_sizes, int n_in,
                              void* d_out, int out_size) {
    const int*   x       = (const int*)d_in[0];
    const float* embed_W = (const float*)d_in[2];
    const float* pd_W    = (const float*)d_in[3];
    const float* pd_b    = (const float*)d_in[4];
    const float* comp_T  = (const float*)d_in[5];
    const float* cl_W    = (const float*)d_in[6];
    const float* cl_b    = (const float*)d_in[7];
    const float* l1_W    = (const float*)d_in[8];
    const float* l1_b    = (const float*)d_in[9];
    const float* l2_W    = (const float*)d_in[10];
    const float* l2_b    = (const float*)d_in[11];
    float* out = (float*)d_out;

    k_prep_small<<<128, 256>>>(pd_W, cl_W, l1_W);
    k_prep_groups<<<1, 256>>>();
    k_prep_spb<<<NC32, 256>>>(comp_T);
    k_prep_l2w<<<(H1 * EM) / 256, 256>>>(l2_W);
    k_cat<<<(2 * BATCH) / 16, 256>>>(x, embed_W, pd_b);

    cudaFuncSetAttribute(k_main_mma, cudaFuncAttributeMaxDynamicSharedMemorySize,
                         SMEM_MAIN);
    k_main_mma<<<BATCH / 128, 256, SMEM_MAIN>>>();

    k_comp<<<BATCH / 32, 256>>>(cl_b, l1_b);
    k_l2_mma<<<dim3(BATCH / 128, EM / 128), 256>>>(l2_b, out);
    k_norm<<<BATCH, 256>>>(out);
}

// round 5
// speedup vs baseline: 4.4281x; 1.2938x over previous
#include <cuda_runtime.h>
#include <cstdint>

#define BATCH 16384
#define NK 100        // TENSOR_DIM
#define D 200         // 2*TENSOR_DIM
#define H1 512        // EMBED_SIZE/2
#define EM 1024       // EMBED_SIZE
#define WD 300        // WORD_DIM

#define PREAL 20400   // real quadratic pair count
#define PLIN  20600   // + 200 linear (term2) pairs
#define PPAD  20608   // padded to 32 (20600 = cl_b pair, 20601+ zero)
#define NGROUP 5152   // PPAD / 4
#define NC32 644      // PPAD / 32

// ---------------- scratch (device globals; no allocation) ----------------
__device__ float g_catT[D * BATCH];            // cat transposed [i][b]
__device__ float g_SpB[PPAD * 120];            // Sp tf32, row-major [p][n(120)]
__device__ int2  g_groups[NGROUP];             // (j, i0) per 4-pair group
__device__ float g_pdWT[WD * NK];
__device__ float g_l1WT[104 * H1];             // [k][m], rows 100..103 stay 0
__device__ float g_l2Wt[H1 * EM];              // l2_W transposed [k][e], tf32 bits
__device__ float g_term1[BATCH * NK];          // term1+term2+cl_b (pre-lrelu)
__device__ float g_h[BATCH * H1];              // tf32 bits

__device__ __forceinline__ float lrelu(float x) { return x >= 0.f ? x : 0.1f * x; }

__device__ __forceinline__ uint32_t smem_u32(const void* p) {
    return (uint32_t)__cvta_generic_to_shared(p);
}
__device__ __forceinline__ uint32_t f2tf32(float x) {
    uint32_t r; asm("cvt.rna.tf32.f32 %0, %1;" : "=r"(r) : "f"(x)); return r;
}
#define CP_ASYNC16(dst, src) \
    asm volatile("cp.async.cg.shared.global [%0], [%1], 16;" :: "r"(dst), "l"(src) : "memory")
#define CP_COMMIT() asm volatile("cp.async.commit_group;" ::: "memory")

__device__ __forceinline__ void mma_tf32(float* d, const uint32_t* a,
                                         uint32_t b0, uint32_t b1) {
    asm volatile(
        "mma.sync.aligned.m16n8k8.row.col.f32.tf32.tf32.f32 "
        "{%0,%1,%2,%3}, {%4,%5,%6,%7}, {%8,%9}, {%0,%1,%2,%3};"
        : "+f"(d[0]), "+f"(d[1]), "+f"(d[2]), "+f"(d[3])
        : "r"(a[0]), "r"(a[1]), "r"(a[2]), "r"(a[3]), "r"(b0), "r"(b1));
}

// ---------------- prep: small transposes ----------------
__global__ void k_prep_small(const float* __restrict__ pd_W,
                             const float* __restrict__ l1_W) {
    int stride = gridDim.x * blockDim.x;
    int t0 = blockIdx.x * blockDim.x + threadIdx.x;
    for (int l = t0; l < WD * NK; l += stride) {
        int c = l / NK, k = l - c * NK;
        g_pdWT[l] = pd_W[k * WD + c];
    }
    for (int l = t0; l < NK * H1; l += stride) {
        int k = l / H1, m = l - k * H1;
        g_l1WT[l] = l1_W[m * NK + k];
    }
}

__global__ void k_prep_l2w(const float* __restrict__ l2_W) {
    int idx = blockIdx.x * 256 + threadIdx.x;       // k*1024 + e
    int k = idx >> 10, e = idx & 1023;
    g_l2Wt[idx] = __uint_as_float(f2tf32(l2_W[e * H1 + k]));
}

// ---------------- prep: pair-group table ----------------
// quadratic pairs: for j=0..199, i from (j & ~3) to 199 (runs multiple of 4)
// linear pairs (term2): j=200 ("ones" column), i = 0..199; then (200,200)=bias
__global__ void k_prep_groups() {
    int j = threadIdx.x;
    if (j < 200) {
        int q = j >> 2, r = j & 3;
        int S = 2 * q * (q - 1) + r * q;
        int gbase = 50 * j - S;
        int i0 = j & ~3;
        int ng = (200 - i0) >> 2;
        for (int g = 0; g < ng; ++g)
            g_groups[gbase + g] = make_int2(j, i0 + 4 * g);
    }
    int idx = j - 200;
    if (idx >= 0 && idx < 50) g_groups[5100 + idx] = make_int2(200, idx * 4);
    if (idx == 50) g_groups[5150] = make_int2(200, 200);  // bias pair (+3 zero)
    if (idx == 51) g_groups[5151] = make_int2(200, 204);  // all-zero pad
}

// ---------------- prep: Sp rows (pairs) x 120 n-cols, tf32 ----------------
__global__ void __launch_bounds__(256) k_prep_spb(const float* __restrict__ T,
                                                  const float* __restrict__ clW,
                                                  const float* __restrict__ clb) {
    int c = blockIdx.x;              // 644 chunks of 32 pairs
    for (int e = threadIdx.x; e < 3840; e += 256) {
        int l = e / 120, n = e - l * 120;
        int p = c * 32 + l;
        float v = 0.f;
        if (n < NK) {
            if (p < PREAL) {
                int2 gi = g_groups[p >> 2];
                int i = gi.y + (p & 3), j = gi.x;
                if (i > j)       v = T[(n * D + i) * D + j] + T[(n * D + j) * D + i];
                else if (i == j) v = T[(n * D + i) * D + i];
            } else if (p < PLIN) {
                v = clW[n * D + (p - PREAL)];
            } else if (p == PLIN) {
                v = clb[n];
            }
        }
        g_SpB[(size_t)p * 120 + n] = __uint_as_float(f2tf32(v));
    }
}

// ---------------- embedding gather + projdown + leaky ----------------
__global__ void __launch_bounds__(256) k_cat(const int* __restrict__ x,
                                             const float* __restrict__ embed_W,
                                             const float* __restrict__ pd_b) {
    __shared__ float e_s[16][WD + 4];
    __shared__ float o_s[NK][17];
    __shared__ int   xs[16];
    int g = blockIdx.x;
    int row0 = g * 16;
    int slot = row0 / BATCH;
    int bbase = row0 - slot * BATCH;
    int t = threadIdx.x;
    if (t < 16) xs[t] = x[(bbase + t) * 2 + slot];
    __syncthreads();
    for (int l = t; l < 16 * WD; l += 256) {
        int r = l / WD, c = l - r * WD;
        e_s[r][c] = embed_W[(size_t)xs[r] * WD + c];
    }
    __syncthreads();
    int k  = t & 127;
    int rt = t >> 7;
    if (k < NK) {
        float acc[8];
#pragma unroll
        for (int q = 0; q < 8; ++q) acc[q] = 0.f;
        for (int c4 = 0; c4 < WD; c4 += 4) {
            float w0 = g_pdWT[(c4 + 0) * NK + k];
            float w1 = g_pdWT[(c4 + 1) * NK + k];
            float w2 = g_pdWT[(c4 + 2) * NK + k];
            float w3 = g_pdWT[(c4 + 3) * NK + k];
#pragma unroll
            for (int q = 0; q < 8; ++q) {
                float4 e = *(const float4*)&e_s[rt + 2 * q][c4];
                acc[q] += e.x * w0 + e.y * w1 + e.z * w2 + e.w * w3;
            }
        }
        float bk = pd_b[k];
#pragma unroll
        for (int q = 0; q < 8; ++q)
            o_s[k][rt + 2 * q] = lrelu(acc[q] + bk);
    }
    __syncthreads();
    for (int l = t; l < NK * 16; l += 256) {
        int kk = l >> 4, col = l & 15;
        g_catT[(slot * NK + kk) * BATCH + bbase + col] = o_s[kk][col];
    }
}

// ---------------- main: term1(+term2+bias) via mma.sync tf32 ----------------
// CTA: 128 b x 112 n, 4 warps, warp tile 32b x 112n (no A duplication).
// K loop: 644 chunks of 32 pairs, cp.async double-buffered.
#define CAT_STRIDE 228            // words; 228 % 32 == 4 -> conflict-free frags
#define SP_OFF   116736           // 128 * 228 * 4
#define SP_BYTES 15360            // 32 * 120 * 4
#define GRP_OFF  (SP_OFF + 2 * SP_BYTES)       // 147456
#define SMEM_MAIN (GRP_OFF + NGROUP * 8)       // 188672

__global__ void __launch_bounds__(128, 1) k_main_mma() {
    extern __shared__ char smem[];
    float* cat = (float*)smem;
    int2*  grp = (int2*)(smem + GRP_OFF);
    uint32_t sb = smem_u32(smem);
    int tid = threadIdx.x, lane = tid & 31, wid = tid >> 5;
    int b0 = blockIdx.x * 128;

    // prologue: kick off chunk 0 load first
    {
        const char* src = (const char*)g_SpB;
        for (int i = tid; i < 960; i += 128)
            CP_ASYNC16(sb + SP_OFF + i * 16, src + i * 16);
        CP_COMMIT();
    }
    for (int l = tid; l < NGROUP; l += 128) grp[l] = g_groups[l];
    for (int l = tid; l < D * 128; l += 128) {
        int i = l >> 7, b = l & 127;
        cat[b * CAT_STRIDE + i] = g_catT[i * BATCH + b0 + b];
    }
    {   // ones column + zero pad (slots 200..207), one row per thread
        float* r = cat + tid * CAT_STRIDE;
        r[200] = 1.f;
#pragma unroll
        for (int s = 201; s < 208; ++s) r[s] = 0.f;
    }

    int R0 = wid * 32;
    int rA = R0 + (lane >> 2);
    int ic = lane & 3;
    int nb = lane >> 2;

    float acc[2][14][4];
#pragma unroll
    for (int f = 0; f < 2; ++f)
#pragma unroll
        for (int t = 0; t < 14; ++t)
#pragma unroll
            for (int q = 0; q < 4; ++q) acc[f][t][q] = 0.f;

    __syncthreads();   // cat + grp ready

    for (int c = 0; c < NC32; ++c) {
        int s = c & 1;
        if (c + 1 < NC32) {
            const char* src = (const char*)g_SpB + (size_t)(c + 1) * SP_BYTES;
            uint32_t dst = sb + SP_OFF + (s ^ 1) * SP_BYTES;
            for (int i = tid; i < 960; i += 128)
                CP_ASYNC16(dst + i * 16, src + i * 16);
            CP_COMMIT();
            asm volatile("cp.async.wait_group 1;" ::: "memory");
        } else {
            asm volatile("cp.async.wait_group 0;" ::: "memory");
        }
        __syncthreads();

        const uint32_t* spu = (const uint32_t*)(smem + SP_OFF + s * SP_BYTES);
        int gb = c * 8;
#pragma unroll
        for (int kk = 0; kk < 4; ++kk) {
            int2 G0 = grp[gb + kk * 2];
            int2 G1 = grp[gb + kk * 2 + 1];
            uint32_t afr[2][4];
#pragma unroll
            for (int f = 0; f < 2; ++f) {
                const float* r0p = cat + (rA + f * 16) * CAT_STRIDE;
                const float* r1p = r0p + 8 * CAT_STRIDE;
                afr[f][0] = f2tf32(r0p[G0.y + ic] * r0p[G0.x]);
                afr[f][1] = f2tf32(r1p[G0.y + ic] * r1p[G0.x]);
                afr[f][2] = f2tf32(r0p[G1.y + ic] * r0p[G1.x]);
                afr[f][3] = f2tf32(r1p[G1.y + ic] * r1p[G1.x]);
            }
            int krow0 = (kk * 8 + ic) * 120;
            int krow1 = krow0 + 4 * 120;
#pragma unroll
            for (int t = 0; t < 14; ++t) {
                uint32_t bb0 = spu[krow0 + nb + t * 8];
                uint32_t bb1 = spu[krow1 + nb + t * 8];
                mma_tf32(acc[0][t], afr[0], bb0, bb1);
                mma_tf32(acc[1][t], afr[1], bb0, bb1);
            }
        }
        __syncthreads();
    }

    // epilogue: write term1 (cols < 100)
    int cb = 2 * ic;
#pragma unroll
    for (int f = 0; f < 2; ++f) {
        int r = b0 + R0 + f * 16 + (lane >> 2);
#pragma unroll
        for (int t = 0; t < 14; ++t) {
            int n0 = cb + t * 8;
            if (n0 < NK) {
                *(float2*)&g_term1[(size_t)r * NK + n0] =
                    make_float2(acc[f][t][0], acc[f][t][1]);
                *(float2*)&g_term1[(size_t)(r + 8) * NK + n0] =
                    make_float2(acc[f][t][2], acc[f][t][3]);
            }
        }
    }
}

// ---------------- hidden layer: h = lrelu(lrelu(term1) @ l1W^T + b), mma ----------------
// CTA 128 b x 128 m, K = 104 (rows 100..103 zero). grid (128, 4).
#define HA_STR 108
#define HB_STR 136
#define HB_OFF 55296                       // 128*108*4
#define SMEM_HID (HB_OFF + 104 * HB_STR * 4)   // 55296 + 56576 = 111872

__global__ void __launch_bounds__(256) k_hid(const float* __restrict__ l1_b) {
    extern __shared__ char sm2[];
    float*    As = (float*)sm2;
    uint32_t* Bs = (uint32_t*)(sm2 + HB_OFF);
    int tid = threadIdx.x, lane = tid & 31, wid = tid >> 5;
    int b0 = blockIdx.x * 128, m0 = blockIdx.y * 128;

    // B: l1WT rows 0..103, cols m0..m0+127 via cp.async
    for (int i = tid; i < 3328; i += 256) {
        int r = i >> 5, q = i & 31;
        CP_ASYNC16(smem_u32(&Bs[r * HB_STR + q * 4]),
                   (const char*)(g_l1WT + r * H1 + m0 + q * 4));
    }
    CP_COMMIT();

    // A: lrelu(term1) -> tf32, 2 threads per row, 52 cols each (pad 100..103 = 0)
    {
        int r = tid >> 1, hf = tid & 1;
        const float* src = g_term1 + (size_t)(b0 + r) * NK;
        float* dst = As + r * HA_STR;
#pragma unroll 4
        for (int q = 0; q < 52; ++q) {
            int cc = hf * 52 + q;
            float v = (cc < NK) ? lrelu(src[cc]) : 0.f;
            dst[cc] = __uint_as_float(f2tf32(v));
        }
    }
    asm volatile("cp.async.wait_group 0;" ::: "memory");
    __syncthreads();

    int rw = wid & 3, cw = wid >> 2;
    int R0 = rw * 32;
    int ic = lane & 3;

    float acc[2][8][4];
#pragma unroll
    for (int f = 0; f < 2; ++f)
#pragma unroll
        for (int t = 0; t < 8; ++t)
#pragma unroll
            for (int q = 0; q < 4; ++q) acc[f][t][q] = 0.f;

#pragma unroll
    for (int kk = 0; kk < 13; ++kk) {
        uint32_t af[2][4];
#pragma unroll
        for (int f = 0; f < 2; ++f) {
            const uint32_t* hp = (const uint32_t*)As +
                (R0 + f * 16 + (lane >> 2)) * HA_STR + kk * 8 + ic;
            af[f][0] = hp[0];
            af[f][1] = hp[8 * HA_STR];
            af[f][2] = hp[4];
            af[f][3] = hp[8 * HA_STR + 4];
        }
        const uint32_t* wp = &Bs[(kk * 8 + ic) * HB_STR + cw * 64 + (lane >> 2)];
#pragma unroll
        for (int t = 0; t < 8; ++t) {
            uint32_t bb0 = wp[t * 8];
            uint32_t bb1 = wp[4 * HB_STR + t * 8];
            mma_tf32(acc[0][t], af[0], bb0, bb1);
            mma_tf32(acc[1][t], af[1], bb0, bb1);
        }
    }

#pragma unroll
    for (int t = 0; t < 8; ++t) {
        int m = m0 + cw * 64 + t * 8 + 2 * ic;
        float bm0 = l1_b[m], bm1 = l1_b[m + 1];
#pragma unroll
        for (int f = 0; f < 2; ++f) {
            int r = b0 + R0 + f * 16 + (lane >> 2);
            float h0 = lrelu(acc[f][t][0] + bm0);
            float h1 = lrelu(acc[f][t][1] + bm1);
            float h2 = lrelu(acc[f][t][2] + bm0);
            float h3 = lrelu(acc[f][t][3] + bm1);
            *(float2*)&g_h[(size_t)r * H1 + m] = make_float2(
                __uint_as_float(f2tf32(h0)), __uint_as_float(f2tf32(h1)));
            *(float2*)&g_h[(size_t)(r + 8) * H1 + m] = make_float2(
                __uint_as_float(f2tf32(h2)), __uint_as_float(f2tf32(h3)));
        }
    }
}

// ---------------- l2 GEMM via mma.sync tf32 ----------------
// CTA 128b x 128e; 8 warps = 4 row-groups x 2 col-groups
__global__ void __launch_bounds__(256) k_l2_mma(const float* __restrict__ l2_b,
                                                float* __restrict__ out) {
    __shared__ uint32_t hs[2][128 * 20];
    __shared__ uint32_t ws[2][16 * 136];
    int tid = threadIdx.x, lane = tid & 31, wid = tid >> 5;
    int b0 = blockIdx.x * 128, e0 = blockIdx.y * 128;
    int rw = wid & 3, cw = wid >> 2;
    int R0 = rw * 32;
    int ic = lane & 3;

    float acc[2][8][4];
#pragma unroll
    for (int f = 0; f < 2; ++f)
#pragma unroll
        for (int t = 0; t < 8; ++t)
#pragma unroll
            for (int q = 0; q < 4; ++q) acc[f][t][q] = 0.f;

    auto issue = [&](int kt, int s) {
        for (int i = tid; i < 512; i += 256) {
            int r = i >> 2, q = i & 3;
            const char* src = (const char*)(g_h + (size_t)(b0 + r) * H1 + kt * 16) + q * 16;
            CP_ASYNC16(smem_u32(&hs[s][r * 20]) + q * 16, src);
        }
        for (int i = tid; i < 512; i += 256) {
            int r = i >> 5, q = i & 31;
            const char* src = (const char*)(g_l2Wt + (size_t)(kt * 16 + r) * EM + e0) + q * 16;
            CP_ASYNC16(smem_u32(&ws[s][r * 136]) + q * 16, src);
        }
        CP_COMMIT();
    };
    issue(0, 0);

    for (int kt = 0; kt < 32; ++kt) {
        int s = kt & 1;
        if (kt + 1 < 32) {
            issue(kt + 1, s ^ 1);
            asm volatile("cp.async.wait_group 1;" ::: "memory");
        } else {
            asm volatile("cp.async.wait_group 0;" ::: "memory");
        }
        __syncthreads();
#pragma unroll
        for (int kk = 0; kk < 2; ++kk) {
            uint32_t af[2][4];
#pragma unroll
            for (int f = 0; f < 2; ++f) {
                const uint32_t* hp =
                    &hs[s][(R0 + f * 16 + (lane >> 2)) * 20 + kk * 8 + ic];
                af[f][0] = hp[0];
                af[f][1] = hp[8 * 20];
                af[f][2] = hp[4];
                af[f][3] = hp[8 * 20 + 4];
            }
            const uint32_t* wp = &ws[s][(kk * 8 + ic) * 136 + cw * 64 + (lane >> 2)];
#pragma unroll
            for (int t = 0; t < 8; ++t) {
                uint32_t bb0 = wp[t * 8];
                uint32_t bb1 = wp[4 * 136 + t * 8];
                mma_tf32(acc[0][t], af[0], bb0, bb1);
                mma_tf32(acc[1][t], af[1], bb0, bb1);
            }
        }
        __syncthreads();
    }

#pragma unroll
    for (int t = 0; t < 8; ++t) {
        int e = e0 + cw * 64 + t * 8 + 2 * ic;
        float be0 = l2_b[e], be1 = l2_b[e + 1];
#pragma unroll
        for (int f = 0; f < 2; ++f) {
            int r = b0 + R0 + f * 16 + (lane >> 2);
            *(float2*)&out[(size_t)r * EM + e] =
                make_float2(acc[f][t][0] + be0, acc[f][t][1] + be1);
            *(float2*)&out[(size_t)(r + 8) * EM + e] =
                make_float2(acc[f][t][2] + be0, acc[f][t][3] + be1);
        }
    }
}

// ---------------- row-wise L2 normalization ----------------
__global__ void __launch_bounds__(256) k_norm(float* __restrict__ out) {
    __shared__ float wsum[8];
    int b = blockIdx.x;
    int t = threadIdx.x;
    float4* row = (float4*)(out + (size_t)b * EM);
    float4 v = row[t];
    float s = v.x * v.x + v.y * v.y + v.z * v.z + v.w * v.w;
#pragma unroll
    for (int off = 16; off > 0; off >>= 1)
        s += __shfl_xor_sync(0xffffffffu, s, off);
    if ((t & 31) == 0) wsum[t >> 5] = s;
    __syncthreads();
    float tot = wsum[0] + wsum[1] + wsum[2] + wsum[3] +
                wsum[4] + wsum[5] + wsum[6] + wsum[7];
    float inv = rsqrtf(tot);
    row[t] = make_float4(v.x * inv, v.y * inv, v.z * inv, v.w * inv);
}

// ---------------- launch ----------------
extern "C" void kernel_launch(void* const* d_in, const int* in_sizes, int n_in,
                              void* d_out, int out_size) {
    const int*   x       = (const int*)d_in[0];
    const float* embed_W = (const float*)d_in[2];
    const float* pd_W    = (const float*)d_in[3];
    const float* pd_b    = (const float*)d_in[4];
    const float* comp_T  = (const float*)d_in[5];
    const float* cl_W    = (const float*)d_in[6];
    const float* cl_b    = (const float*)d_in[7];
    const float* l1_W    = (const float*)d_in[8];
    const float* l1_b    = (const float*)d_in[9];
    const float* l2_W    = (const float*)d_in[10];
    const float* l2_b    = (const float*)d_in[11];
    float* out = (float*)d_out;

    k_prep_groups<<<1, 256>>>();
    k_prep_small<<<128, 256>>>(pd_W, l1_W);
    k_prep_spb<<<NC32, 256>>>(comp_T, cl_W, cl_b);
    k_prep_l2w<<<(H1 * EM) / 256, 256>>>(l2_W);
    k_cat<<<(2 * BATCH) / 16, 256>>>(x, embed_W, pd_b);

    cudaFuncSetAttribute(k_main_mma, cudaFuncAttributeMaxDynamicSharedMemorySize,
                         SMEM_MAIN);
    k_main_mma<<<BATCH / 128, 128, SMEM_MAIN>>>();

    cudaFuncSetAttribute(k_hid, cudaFuncAttributeMaxDynamicSharedMemorySize,
                         SMEM_HID);
    k_hid<<<dim3(BATCH / 128, 4), 256, SMEM_HID>>>(l1_b);

    k_l2_mma<<<dim3(BATCH / 128, EM / 128), 256>>>(l2_b, out);
    k_norm<<<BATCH, 256>>>(out);
}

// round 7
// speedup vs baseline: 5.2397x; 1.1833x over previous
#include <cuda_runtime.h>
#include <cuda_fp16.h>
#include <cstdint>

#define BATCH 16384
#define NK 100        // TENSOR_DIM
#define D 200         // 2*TENSOR_DIM
#define H1 512        // EMBED_SIZE/2
#define EM 1024       // EMBED_SIZE
#define WD 300        // WORD_DIM

#define PREAL 20400   // real quadratic pair count
#define PLIN  20600   // + 200 linear (term2) pairs
#define PPAD  20608   // padded to 32 (20600 = cl_b pair, rest zero)
#define NGROUP 5152   // PPAD / 4
#define NC32 644      // PPAD / 32
#define SPB_CHUNK 7680   // 120 n-rows * 32 p * 2B

// ---------------- scratch (device globals; no allocation) ----------------
__device__ float g_catT[D * BATCH];               // cat transposed [i][b]
__device__ unsigned char g_SpB[NC32 * SPB_CHUNK]; // Sp fp16, swizzled [c][n][p]
__device__ int2  g_groups[NGROUP];                // (j, i0) per 4-pair group
__device__ float g_pdWT[WD * NK];
__device__ float g_l1WT[104 * H1];                // [k][m], rows 100..103 zero
__device__ unsigned char g_l2Wh[EM * H1 * 2];     // l2_W fp16 [e][k]
__device__ float g_term1[BATCH * NK];             // term1+term2+cl_b (pre-lrelu)
__device__ uint32_t g_hu[BATCH * 256];            // h as packed half2 [b][256]

__device__ __forceinline__ float lrelu(float x) { return x >= 0.f ? x : 0.1f * x; }

__device__ __forceinline__ uint32_t smem_u32(const void* p) {
    return (uint32_t)__cvta_generic_to_shared(p);
}
__device__ __forceinline__ uint32_t f2tf32(float x) {
    uint32_t r; asm("cvt.rna.tf32.f32 %0, %1;" : "=r"(r) : "f"(x)); return r;
}
__device__ __forceinline__ uint32_t pack_h2(float lo, float hi) {
    __half2 h = __floats2half2_rn(lo, hi);
    return *(uint32_t*)&h;
}
#define CP_ASYNC16(dst, src) \
    asm volatile("cp.async.cg.shared.global [%0], [%1], 16;" :: "r"(dst), "l"(src) : "memory")
#define CP_COMMIT() asm volatile("cp.async.commit_group;" ::: "memory")

__device__ __forceinline__ void mma_tf32(float* d, const uint32_t* a,
                                         uint32_t b0, uint32_t b1) {
    asm volatile(
        "mma.sync.aligned.m16n8k8.row.col.f32.tf32.tf32.f32 "
        "{%0,%1,%2,%3}, {%4,%5,%6,%7}, {%8,%9}, {%0,%1,%2,%3};"
        : "+f"(d[0]), "+f"(d[1]), "+f"(d[2]), "+f"(d[3])
        : "r"(a[0]), "r"(a[1]), "r"(a[2]), "r"(a[3]), "r"(b0), "r"(b1));
}
__device__ __forceinline__ void mma_f16(float* d, const uint32_t* a,
                                        uint32_t b0, uint32_t b1) {
    asm volatile(
        "mma.sync.aligned.m16n8k16.row.col.f32.f16.f16.f32 "
        "{%0,%1,%2,%3}, {%4,%5,%6,%7}, {%8,%9}, {%0,%1,%2,%3};"
        : "+f"(d[0]), "+f"(d[1]), "+f"(d[2]), "+f"(d[3])
        : "r"(a[0]), "r"(a[1]), "r"(a[2]), "r"(a[3]), "r"(b0), "r"(b1));
}

// ---------------- prep: small transposes ----------------
__global__ void k_prep_small(const float* __restrict__ pd_W,
                             const float* __restrict__ l1_W) {
    int stride = gridDim.x * blockDim.x;
    int t0 = blockIdx.x * blockDim.x + threadIdx.x;
    for (int l = t0; l < WD * NK; l += stride) {
        int c = l / NK, k = l - c * NK;
        g_pdWT[l] = pd_W[k * WD + c];
    }
    for (int l = t0; l < NK * H1; l += stride) {
        int k = l / H1, m = l - k * H1;
        g_l1WT[l] = l1_W[m * NK + k];
    }
}

__global__ void k_prep_l2h(const float* __restrict__ l2_W) {
    int idx = blockIdx.x * 256 + threadIdx.x;       // e*512 + k
    ((__half*)g_l2Wh)[idx] = __float2half_rn(l2_W[idx]);
}

// ---------------- prep: pair-group table ----------------
__global__ void k_prep_groups() {
    int j = threadIdx.x;
    if (j < 200) {
        int q = j >> 2, r = j & 3;
        int S = 2 * q * (q - 1) + r * q;
        int gbase = 50 * j - S;
        int i0 = j & ~3;
        int ng = (200 - i0) >> 2;
        for (int g = 0; g < ng; ++g)
            g_groups[gbase + g] = make_int2(j, i0 + 4 * g);
    }
    int idx = j - 200;
    if (idx >= 0 && idx < 50) g_groups[5100 + idx] = make_int2(200, idx * 4);
    if (idx == 50) g_groups[5150] = make_int2(200, 200);  // bias pair
    if (idx == 51) g_groups[5151] = make_int2(200, 204);  // zero pad
}

// ---------------- prep: Sp fp16, [chunk][n(120)][32 p] with block swizzle ----
// row stride = 64 BYTES (32 halfs). (R6 bug: was n*32 -> rows overlapped.)
__global__ void __launch_bounds__(256) k_prep_spb(const float* __restrict__ T,
                                                  const float* __restrict__ clW,
                                                  const float* __restrict__ clb) {
    int c = blockIdx.x;
    unsigned char* base = g_SpB + (size_t)c * SPB_CHUNK;
    for (int e = threadIdx.x; e < 3840; e += 256) {
        int n = e >> 5, pl = e & 31;
        int p = c * 32 + pl;
        float v = 0.f;
        if (n < NK) {
            if (p < PREAL) {
                int2 gi = g_groups[p >> 2];
                int i = gi.y + (p & 3), j = gi.x;
                if (i > j)       v = T[(n * D + i) * D + j] + T[(n * D + j) * D + i];
                else if (i == j) v = T[(n * D + i) * D + i];
            } else if (p < PLIN) {
                v = clW[n * D + (p - PREAL)];
            } else if (p == PLIN) {
                v = clb[n];
            }
        }
        int w = pl >> 1;
        int sg = ((n >> 1) & 3) << 2;
        int off = n * 64 + ((w ^ sg) << 2) + (pl & 1) * 2;
        *(__half*)(base + off) = __float2half_rn(v);
    }
}

// ---------------- embedding gather + projdown + leaky ----------------
__global__ void __launch_bounds__(256) k_cat(const int* __restrict__ x,
                                             const float* __restrict__ embed_W,
                                             const float* __restrict__ pd_b) {
    __shared__ float e_s[16][WD + 4];
    __shared__ float o_s[NK][17];
    __shared__ int   xs[16];
    int g = blockIdx.x;
    int row0 = g * 16;
    int slot = row0 / BATCH;
    int bbase = row0 - slot * BATCH;
    int t = threadIdx.x;
    if (t < 16) xs[t] = x[(bbase + t) * 2 + slot];
    __syncthreads();
    for (int l = t; l < 16 * WD; l += 256) {
        int r = l / WD, c = l - r * WD;
        e_s[r][c] = embed_W[(size_t)xs[r] * WD + c];
    }
    __syncthreads();
    int k  = t & 127;
    int rt = t >> 7;
    if (k < NK) {
        float acc[8];
#pragma unroll
        for (int q = 0; q < 8; ++q) acc[q] = 0.f;
        for (int c4 = 0; c4 < WD; c4 += 4) {
            float w0 = g_pdWT[(c4 + 0) * NK + k];
            float w1 = g_pdWT[(c4 + 1) * NK + k];
            float w2 = g_pdWT[(c4 + 2) * NK + k];
            float w3 = g_pdWT[(c4 + 3) * NK + k];
#pragma unroll
            for (int q = 0; q < 8; ++q) {
                float4 e = *(const float4*)&e_s[rt + 2 * q][c4];
                acc[q] += e.x * w0 + e.y * w1 + e.z * w2 + e.w * w3;
            }
        }
        float bk = pd_b[k];
#pragma unroll
        for (int q = 0; q < 8; ++q)
            o_s[k][rt + 2 * q] = lrelu(acc[q] + bk);
    }
    __syncthreads();
    for (int l = t; l < NK * 16; l += 256) {
        int kk = l >> 4, col = l & 15;
        g_catT[(slot * NK + kk) * BATCH + bbase + col] = o_s[kk][col];
    }
}

// ---------------- main: term1(+term2+bias) via mma.sync fp16 ----------------
// CTA: 128 b x 112 n, 4 warps, warp tile 32b x 112n. fp16 m16n8k16.
#define CAT_STRIDE 228            // words
#define SP_OFF   116736           // 128 * 228 * 4
#define GRP_OFF  (SP_OFF + 2 * SPB_CHUNK)      // 132096
#define SMEM_MAIN (GRP_OFF + NGROUP * 8)       // 173312

__global__ void __launch_bounds__(128, 1) k_main_mma() {
    extern __shared__ char smem[];
    float* cat = (float*)smem;
    int2*  grp = (int2*)(smem + GRP_OFF);
    uint32_t sb = smem_u32(smem);
    int tid = threadIdx.x, lane = tid & 31, wid = tid >> 5;
    int b0 = blockIdx.x * 128;

    // prologue: kick off chunk 0 load
    {
        const char* src = (const char*)g_SpB;
        for (int i = tid; i < SPB_CHUNK / 16; i += 128)
            CP_ASYNC16(sb + SP_OFF + i * 16, src + i * 16);
        CP_COMMIT();
    }
    for (int l = tid; l < NGROUP; l += 128) grp[l] = g_groups[l];
    for (int l = tid; l < D * 128; l += 128) {
        int i = l >> 7, b = l & 127;
        cat[b * CAT_STRIDE + i] = g_catT[i * BATCH + b0 + b];
    }
    {   // ones column + zero pad (slots 200..207)
        float* r = cat + tid * CAT_STRIDE;
        r[200] = 1.f;
#pragma unroll
        for (int s = 201; s < 208; ++s) r[s] = 0.f;
    }

    int gid = lane >> 2;      // 0..7
    int tc  = lane & 3;       // 0..3
    int R0 = wid * 32;
    int rA = R0 + gid;
    int oa = (tc & 1) * 2;    // i offset within group
    int gsel = tc >> 1;       // which of 2 sub-groups
    // B word offsets (conflict-free via block swizzle)
    int sgB = ((gid >> 1) & 3) << 2;
    int ob[2][2];
#pragma unroll
    for (int s = 0; s < 2; ++s) {
        ob[s][0] = gid * 16 + ((s * 8 + tc) ^ sgB);
        ob[s][1] = gid * 16 + ((s * 8 + tc + 4) ^ sgB);
    }

    float acc[2][14][4];
#pragma unroll
    for (int f = 0; f < 2; ++f)
#pragma unroll
        for (int t = 0; t < 14; ++t)
#pragma unroll
            for (int q = 0; q < 4; ++q) acc[f][t][q] = 0.f;

    __syncthreads();   // cat + grp ready

    for (int c = 0; c < NC32; ++c) {
        int s = c & 1;
        if (c + 1 < NC32) {
            const char* src = (const char*)g_SpB + (size_t)(c + 1) * SPB_CHUNK;
            uint32_t dst = sb + SP_OFF + (s ^ 1) * SPB_CHUNK;
            for (int i = tid; i < SPB_CHUNK / 16; i += 128)
                CP_ASYNC16(dst + i * 16, src + i * 16);
            CP_COMMIT();
            asm volatile("cp.async.wait_group 1;" ::: "memory");
        } else {
            asm volatile("cp.async.wait_group 0;" ::: "memory");
        }
        __syncthreads();

        const uint32_t* spu = (const uint32_t*)(smem + SP_OFF + s * SPB_CHUNK);
        int gb = c * 8;
#pragma unroll
        for (int ks = 0; ks < 2; ++ks) {       // two k16 steps per 32-pair chunk
            int2 Ga = grp[gb + ks * 4 + gsel];
            int2 Gb = grp[gb + ks * 4 + 2 + gsel];
            uint32_t afr[2][4];
#pragma unroll
            for (int f = 0; f < 2; ++f) {
                const float* r0 = cat + (rA + f * 16) * CAT_STRIDE;
                const float* r1 = r0 + 8 * CAT_STRIDE;
                float  ja0 = r0[Ga.x], ja1 = r1[Ga.x];
                float  jb0 = r0[Gb.x], jb1 = r1[Gb.x];
                float2 ia0 = *(const float2*)&r0[Ga.y + oa];
                float2 ia1 = *(const float2*)&r1[Ga.y + oa];
                float2 ib0 = *(const float2*)&r0[Gb.y + oa];
                float2 ib1 = *(const float2*)&r1[Gb.y + oa];
                afr[f][0] = pack_h2(ia0.x * ja0, ia0.y * ja0);
                afr[f][1] = pack_h2(ia1.x * ja1, ia1.y * ja1);
                afr[f][2] = pack_h2(ib0.x * jb0, ib0.y * jb0);
                afr[f][3] = pack_h2(ib1.x * jb1, ib1.y * jb1);
            }
            int o0 = ob[ks][0], o1 = ob[ks][1];
#pragma unroll
            for (int t = 0; t < 14; ++t) {
                uint32_t bb0 = spu[o0 + t * 128];
                uint32_t bb1 = spu[o1 + t * 128];
                mma_f16(acc[0][t], afr[0], bb0, bb1);
                mma_f16(acc[1][t], afr[1], bb0, bb1);
            }
        }
        __syncthreads();
    }

    // epilogue: write term1 (cols < 100)
    int cb = 2 * tc;
#pragma unroll
    for (int f = 0; f < 2; ++f) {
        int r = b0 + R0 + f * 16 + gid;
#pragma unroll
        for (int t = 0; t < 14; ++t) {
            int n0 = cb + t * 8;
            if (n0 < NK) {
                *(float2*)&g_term1[(size_t)r * NK + n0] =
                    make_float2(acc[f][t][0], acc[f][t][1]);
                *(float2*)&g_term1[(size_t)(r + 8) * NK + n0] =
                    make_float2(acc[f][t][2], acc[f][t][3]);
            }
        }
    }
}

// ---------------- hidden: h = lrelu(lrelu(term1) @ l1W^T + b), tf32 mma ----------------
#define HA_STR 108
#define HB_STR 136
#define HB_OFF 55296
#define SMEM_HID (HB_OFF + 104 * HB_STR * 4)

__global__ void __launch_bounds__(256) k_hid(const float* __restrict__ l1_b) {
    extern __shared__ char sm2[];
    float*    As = (float*)sm2;
    uint32_t* Bs = (uint32_t*)(sm2 + HB_OFF);
    int tid = threadIdx.x, lane = tid & 31, wid = tid >> 5;
    int b0 = blockIdx.x * 128, m0 = blockIdx.y * 128;

    for (int i = tid; i < 3328; i += 256) {
        int r = i >> 5, q = i & 31;
        CP_ASYNC16(smem_u32(&Bs[r * HB_STR + q * 4]),
                   (const char*)(g_l1WT + r * H1 + m0 + q * 4));
    }
    CP_COMMIT();

    {
        int r = tid >> 1, hf = tid & 1;
        const float* src = g_term1 + (size_t)(b0 + r) * NK;
        float* dst = As + r * HA_STR;
#pragma unroll 4
        for (int q = 0; q < 52; ++q) {
            int cc = hf * 52 + q;
            float v = (cc < NK) ? lrelu(src[cc]) : 0.f;
            dst[cc] = __uint_as_float(f2tf32(v));
        }
    }
    asm volatile("cp.async.wait_group 0;" ::: "memory");
    __syncthreads();

    int rw = wid & 3, cw = wid >> 2;
    int R0 = rw * 32;
    int ic = lane & 3;

    float acc[2][8][4];
#pragma unroll
    for (int f = 0; f < 2; ++f)
#pragma unroll
        for (int t = 0; t < 8; ++t)
#pragma unroll
            for (int q = 0; q < 4; ++q) acc[f][t][q] = 0.f;

#pragma unroll
    for (int kk = 0; kk < 13; ++kk) {
        uint32_t af[2][4];
#pragma unroll
        for (int f = 0; f < 2; ++f) {
            const uint32_t* hp = (const uint32_t*)As +
                (R0 + f * 16 + (lane >> 2)) * HA_STR + kk * 8 + ic;
            af[f][0] = hp[0];
            af[f][1] = hp[8 * HA_STR];
            af[f][2] = hp[4];
            af[f][3] = hp[8 * HA_STR + 4];
        }
        const uint32_t* wp = &Bs[(kk * 8 + ic) * HB_STR + cw * 64 + (lane >> 2)];
#pragma unroll
        for (int t = 0; t < 8; ++t) {
            uint32_t bb0 = wp[t * 8];
            uint32_t bb1 = wp[4 * HB_STR + t * 8];
            mma_tf32(acc[0][t], af[0], bb0, bb1);
            mma_tf32(acc[1][t], af[1], bb0, bb1);
        }
    }

#pragma unroll
    for (int t = 0; t < 8; ++t) {
        int m = m0 + cw * 64 + t * 8 + 2 * ic;
        float bm0 = l1_b[m], bm1 = l1_b[m + 1];
#pragma unroll
        for (int f = 0; f < 2; ++f) {
            int r = b0 + R0 + f * 16 + (lane >> 2);
            g_hu[(size_t)r * 256 + (m >> 1)] =
                pack_h2(lrelu(acc[f][t][0] + bm0), lrelu(acc[f][t][1] + bm1));
            g_hu[(size_t)(r + 8) * 256 + (m >> 1)] =
                pack_h2(lrelu(acc[f][t][2] + bm0), lrelu(acc[f][t][3] + bm1));
        }
    }
}

// ---------------- l2 GEMM via mma.sync fp16 ----------------
// CTA 128b x 128e; 8 warps = 4 row-groups x 2 col-groups; k staged 16 at a time.
#define L2_STR 12   // words per row (8 used + 4 pad)
__global__ void __launch_bounds__(256) k_l2_mma(const float* __restrict__ l2_b,
                                                float* __restrict__ out) {
    __shared__ uint32_t hs[2][128 * L2_STR];
    __shared__ uint32_t ws[2][128 * L2_STR];
    int tid = threadIdx.x, lane = tid & 31, wid = tid >> 5;
    int b0 = blockIdx.x * 128, e0 = blockIdx.y * 128;
    int rw = wid & 3, cw = wid >> 2;
    int R0 = rw * 32;
    int gid = lane >> 2, tc = lane & 3;

    float acc[2][8][4];
#pragma unroll
    for (int f = 0; f < 2; ++f)
#pragma unroll
        for (int t = 0; t < 8; ++t)
#pragma unroll
            for (int q = 0; q < 4; ++q) acc[f][t][q] = 0.f;

    auto issue = [&](int kt, int s) {
        {
            int r = tid >> 1, q = tid & 1;
            const char* src = (const char*)(g_hu + (size_t)(b0 + r) * 256 + kt * 8) + q * 16;
            CP_ASYNC16(smem_u32(&hs[s][r * L2_STR]) + q * 16, src);
        }
        {
            int r = tid >> 1, q = tid & 1;
            const char* src = (const char*)g_l2Wh + ((size_t)(e0 + r) * 512 + kt * 16) * 2 + q * 16;
            CP_ASYNC16(smem_u32(&ws[s][r * L2_STR]) + q * 16, src);
        }
        CP_COMMIT();
    };
    issue(0, 0);

    for (int kt = 0; kt < 32; ++kt) {
        int s = kt & 1;
        if (kt + 1 < 32) {
            issue(kt + 1, s ^ 1);
            asm volatile("cp.async.wait_group 1;" ::: "memory");
        } else {
            asm volatile("cp.async.wait_group 0;" ::: "memory");
        }
        __syncthreads();

        uint32_t af[2][4];
#pragma unroll
        for (int f = 0; f < 2; ++f) {
            const uint32_t* hp = &hs[s][(R0 + f * 16 + gid) * L2_STR];
            af[f][0] = hp[tc];
            af[f][1] = hp[8 * L2_STR + tc];
            af[f][2] = hp[tc + 4];
            af[f][3] = hp[8 * L2_STR + tc + 4];
        }
        const uint32_t* wp = &ws[s][(cw * 64 + gid) * L2_STR];
#pragma unroll
        for (int t = 0; t < 8; ++t) {
            uint32_t bb0 = wp[t * 8 * L2_STR + tc];
            uint32_t bb1 = wp[t * 8 * L2_STR + tc + 4];
            mma_f16(acc[0][t], af[0], bb0, bb1);
            mma_f16(acc[1][t], af[1], bb0, bb1);
        }
        __syncthreads();
    }

#pragma unroll
    for (int t = 0; t < 8; ++t) {
        int e = e0 + cw * 64 + t * 8 + 2 * tc;
        float be0 = l2_b[e], be1 = l2_b[e + 1];
#pragma unroll
        for (int f = 0; f < 2; ++f) {
            int r = b0 + R0 + f * 16 + gid;
            *(float2*)&out[(size_t)r * EM + e] =
                make_float2(acc[f][t][0] + be0, acc[f][t][1] + be1);
            *(float2*)&out[(size_t)(r + 8) * EM + e] =
                make_float2(acc[f][t][2] + be0, acc[f][t][3] + be1);
        }
    }
}

// ---------------- row-wise L2 normalization ----------------
__global__ void __launch_bounds__(256) k_norm(float* __restrict__ out) {
    __shared__ float wsum[8];
    int b = blockIdx.x;
    int t = threadIdx.x;
    float4* row = (float4*)(out + (size_t)b * EM);
    float4 v = row[t];
    float s = v.x * v.x + v.y * v.y + v.z * v.z + v.w * v.w;
#pragma unroll
    for (int off = 16; off > 0; off >>= 1)
        s += __shfl_xor_sync(0xffffffffu, s, off);
    if ((t & 31) == 0) wsum[t >> 5] = s;
    __syncthreads();
    float tot = wsum[0] + wsum[1] + wsum[2] + wsum[3] +
                wsum[4] + wsum[5] + wsum[6] + wsum[7];
    float inv = rsqrtf(tot);
    row[t] = make_float4(v.x * inv, v.y * inv, v.z * inv, v.w * inv);
}

// ---------------- launch ----------------
extern "C" void kernel_launch(void* const* d_in, const int* in_sizes, int n_in,
                              void* d_out, int out_size) {
    const int*   x       = (const int*)d_in[0];
    const float* embed_W = (const float*)d_in[2];
    const float* pd_W    = (const float*)d_in[3];
    const float* pd_b    = (const float*)d_in[4];
    const float* comp_T  = (const float*)d_in[5];
    const float* cl_W    = (const float*)d_in[6];
    const float* cl_b    = (const float*)d_in[7];
    const float* l1_W    = (const float*)d_in[8];
    const float* l1_b    = (const float*)d_in[9];
    const float* l2_W    = (const float*)d_in[10];
    const float* l2_b    = (const float*)d_in[11];
    float* out = (float*)d_out;

    k_prep_groups<<<1, 256>>>();
    k_prep_small<<<128, 256>>>(pd_W, l1_W);
    k_prep_spb<<<NC32, 256>>>(comp_T, cl_W, cl_b);
    k_prep_l2h<<<(H1 * EM) / 256, 256>>>(l2_W);
    k_cat<<<(2 * BATCH) / 16, 256>>>(x, embed_W, pd_b);

    cudaFuncSetAttribute(k_main_mma, cudaFuncAttributeMaxDynamicSharedMemorySize,
                         SMEM_MAIN);
    k_main_mma<<<BATCH / 128, 128, SMEM_MAIN>>>();

    cudaFuncSetAttribute(k_hid, cudaFuncAttributeMaxDynamicSharedMemorySize,
                         SMEM_HID);
    k_hid<<<dim3(BATCH / 128, 4), 256, SMEM_HID>>>(l1_b);

    k_l2_mma<<<dim3(BATCH / 128, EM / 128), 256>>>(l2_b, out);
    k_norm<<<BATCH, 256>>>(out);
}

// round 8
// speedup vs baseline: 5.4373x; 1.0377x over previous
#include <cuda_runtime.h>
#include <cuda_fp16.h>
#include <cstdint>

#define BATCH 16384
#define NK 100        // TENSOR_DIM
#define D 200         // 2*TENSOR_DIM
#define H1 512        // EMBED_SIZE/2
#define EM 1024       // EMBED_SIZE
#define WD 300        // WORD_DIM

#define PREAL 20400   // real quadratic pair count
#define PLIN  20600   // + 200 linear (term2) pairs
#define PPAD  20608   // padded to 32 (20600 = cl_b pair, rest zero)
#define NGROUP 5152   // PPAD / 4
#define NC32 644      // PPAD / 32
#define SPB_CHUNK 7680   // 120 n-rows * 32 p * 2B

// ---------------- scratch (device globals; no allocation) ----------------
__device__ float g_catT[D * BATCH];               // cat transposed [i][b]
__device__ unsigned char g_SpB[NC32 * SPB_CHUNK]; // Sp fp16, swizzled [c][n][p]
__device__ int2  g_groups[NGROUP];                // (j, i0) per 4-pair group
__device__ uint16_t g_gpk[NGROUP];                // packed (i0<<8)|j
__device__ float g_pdWT[WD * NK];
__device__ float g_l1WT[104 * H1];                // [k][m], rows 100..103 zero
__device__ unsigned char g_l2Wh[EM * H1 * 2];     // l2_W fp16 [e][k]
__device__ float g_term1[BATCH * NK];             // term1+term2+cl_b (pre-lrelu)
__device__ uint32_t g_hu[BATCH * 256];            // h as packed half2 [b][256]

__device__ __forceinline__ float lrelu(float x) { return x >= 0.f ? x : 0.1f * x; }

__device__ __forceinline__ uint32_t smem_u32(const void* p) {
    return (uint32_t)__cvta_generic_to_shared(p);
}
__device__ __forceinline__ uint32_t f2tf32(float x) {
    uint32_t r; asm("cvt.rna.tf32.f32 %0, %1;" : "=r"(r) : "f"(x)); return r;
}
__device__ __forceinline__ uint32_t pack_h2(float lo, float hi) {
    __half2 h = __floats2half2_rn(lo, hi);
    return *(uint32_t*)&h;
}
#define CP_ASYNC16(dst, src) \
    asm volatile("cp.async.cg.shared.global [%0], [%1], 16;" :: "r"(dst), "l"(src) : "memory")
#define CP_COMMIT() asm volatile("cp.async.commit_group;" ::: "memory")

__device__ __forceinline__ void mma_tf32(float* d, const uint32_t* a,
                                         uint32_t b0, uint32_t b1) {
    asm volatile(
        "mma.sync.aligned.m16n8k8.row.col.f32.tf32.tf32.f32 "
        "{%0,%1,%2,%3}, {%4,%5,%6,%7}, {%8,%9}, {%0,%1,%2,%3};"
        : "+f"(d[0]), "+f"(d[1]), "+f"(d[2]), "+f"(d[3])
        : "r"(a[0]), "r"(a[1]), "r"(a[2]), "r"(a[3]), "r"(b0), "r"(b1));
}
__device__ __forceinline__ void mma_f16(float* d, const uint32_t* a,
                                        uint32_t b0, uint32_t b1) {
    asm volatile(
        "mma.sync.aligned.m16n8k16.row.col.f32.f16.f16.f32 "
        "{%0,%1,%2,%3}, {%4,%5,%6,%7}, {%8,%9}, {%0,%1,%2,%3};"
        : "+f"(d[0]), "+f"(d[1]), "+f"(d[2]), "+f"(d[3])
        : "r"(a[0]), "r"(a[1]), "r"(a[2]), "r"(a[3]), "r"(b0), "r"(b1));
}

// ---------------- prep: small transposes ----------------
__global__ void k_prep_small(const float* __restrict__ pd_W,
                             const float* __restrict__ l1_W) {
    int stride = gridDim.x * blockDim.x;
    int t0 = blockIdx.x * blockDim.x + threadIdx.x;
    for (int l = t0; l < WD * NK; l += stride) {
        int c = l / NK, k = l - c * NK;
        g_pdWT[l] = pd_W[k * WD + c];
    }
    for (int l = t0; l < NK * H1; l += stride) {
        int k = l / H1, m = l - k * H1;
        g_l1WT[l] = l1_W[m * NK + k];
    }
}

__global__ void k_prep_l2h(const float* __restrict__ l2_W) {
    int idx = blockIdx.x * 256 + threadIdx.x;       // e*512 + k
    ((__half*)g_l2Wh)[idx] = __float2half_rn(l2_W[idx]);
}

// ---------------- prep: pair-group table (int2 + packed u16) ----------------
__global__ void k_prep_groups() {
    int j = threadIdx.x;
    if (j < 200) {
        int q = j >> 2, r = j & 3;
        int S = 2 * q * (q - 1) + r * q;
        int gbase = 50 * j - S;
        int i0 = j & ~3;
        int ng = (200 - i0) >> 2;
        for (int g = 0; g < ng; ++g) {
            int ii = i0 + 4 * g;
            g_groups[gbase + g] = make_int2(j, ii);
            g_gpk[gbase + g] = (uint16_t)((ii << 8) | j);
        }
    }
    int idx = j - 200;
    if (idx >= 0 && idx < 50) {
        g_groups[5100 + idx] = make_int2(200, idx * 4);
        g_gpk[5100 + idx] = (uint16_t)(((idx * 4) << 8) | 200);
    }
    if (idx == 50) { g_groups[5150] = make_int2(200, 200);
                     g_gpk[5150] = (uint16_t)((200 << 8) | 200); }
    if (idx == 51) { g_groups[5151] = make_int2(200, 204);
                     g_gpk[5151] = (uint16_t)((204 << 8) | 200); }
}

// ---------------- prep: Sp fp16, [chunk][n(120)][32 p] with block swizzle ----
__global__ void __launch_bounds__(256) k_prep_spb(const float* __restrict__ T,
                                                  const float* __restrict__ clW,
                                                  const float* __restrict__ clb) {
    int c = blockIdx.x;
    unsigned char* base = g_SpB + (size_t)c * SPB_CHUNK;
    for (int e = threadIdx.x; e < 3840; e += 256) {
        int n = e >> 5, pl = e & 31;
        int p = c * 32 + pl;
        float v = 0.f;
        if (n < NK) {
            if (p < PREAL) {
                int2 gi = g_groups[p >> 2];
                int i = gi.y + (p & 3), j = gi.x;
                if (i > j)       v = T[(n * D + i) * D + j] + T[(n * D + j) * D + i];
                else if (i == j) v = T[(n * D + i) * D + i];
            } else if (p < PLIN) {
                v = clW[n * D + (p - PREAL)];
            } else if (p == PLIN) {
                v = clb[n];
            }
        }
        int w = pl >> 1;
        int sg = ((n >> 1) & 3) << 2;
        int off = n * 64 + ((w ^ sg) << 2) + (pl & 1) * 2;
        *(__half*)(base + off) = __float2half_rn(v);
    }
}

// ---------------- embedding gather + projdown + leaky ----------------
__global__ void __launch_bounds__(256) k_cat(const int* __restrict__ x,
                                             const float* __restrict__ embed_W,
                                             const float* __restrict__ pd_b) {
    __shared__ float e_s[16][WD + 4];
    __shared__ float o_s[NK][17];
    __shared__ int   xs[16];
    int g = blockIdx.x;
    int row0 = g * 16;
    int slot = row0 / BATCH;
    int bbase = row0 - slot * BATCH;
    int t = threadIdx.x;
    if (t < 16) xs[t] = x[(bbase + t) * 2 + slot];
    __syncthreads();
    for (int l = t; l < 16 * WD; l += 256) {
        int r = l / WD, c = l - r * WD;
        e_s[r][c] = embed_W[(size_t)xs[r] * WD + c];
    }
    __syncthreads();
    int k  = t & 127;
    int rt = t >> 7;
    if (k < NK) {
        float acc[8];
#pragma unroll
        for (int q = 0; q < 8; ++q) acc[q] = 0.f;
        for (int c4 = 0; c4 < WD; c4 += 4) {
            float w0 = g_pdWT[(c4 + 0) * NK + k];
            float w1 = g_pdWT[(c4 + 1) * NK + k];
            float w2 = g_pdWT[(c4 + 2) * NK + k];
            float w3 = g_pdWT[(c4 + 3) * NK + k];
#pragma unroll
            for (int q = 0; q < 8; ++q) {
                float4 e = *(const float4*)&e_s[rt + 2 * q][c4];
                acc[q] += e.x * w0 + e.y * w1 + e.z * w2 + e.w * w3;
            }
        }
        float bk = pd_b[k];
#pragma unroll
        for (int q = 0; q < 8; ++q)
            o_s[k][rt + 2 * q] = lrelu(acc[q] + bk);
    }
    __syncthreads();
    for (int l = t; l < NK * 16; l += 256) {
        int kk = l >> 4, col = l & 15;
        g_catT[(slot * NK + kk) * BATCH + bbase + col] = o_s[kk][col];
    }
}

// ---------------- main: term1(+term2+bias) via mma.sync fp16 ----------------
// CTA: 64 b x 104 n, 4 warps (warp tile 16b x 104n), 2 CTAs/SM.
// K loop: 644 chunks of 32 pairs, cp.async double-buffered (104 n-rows only).
#define CAT_STRIDE 228                          // words
#define SP_OFF   58368                          // 64 * 228 * 4
#define GRP_OFF  (SP_OFF + 2 * SPB_CHUNK)       // 73728
#define SMEM_MAIN (GRP_OFF + NGROUP * 2)        // 84032
#define BLOAD 416                               // 104 n-rows * 64B / 16

__global__ void __launch_bounds__(128, 2) k_main_mma() {
    extern __shared__ char smem[];
    float* cat = (float*)smem;
    uint16_t* grp = (uint16_t*)(smem + GRP_OFF);
    uint32_t sb = smem_u32(smem);
    int tid = threadIdx.x, lane = tid & 31, wid = tid >> 5;
    int b0 = blockIdx.x * 64;

    // prologue: kick off chunk 0 B load
    {
        const char* src = (const char*)g_SpB;
        for (int i = tid; i < BLOAD; i += 128)
            CP_ASYNC16(sb + SP_OFF + i * 16, src + i * 16);
        CP_COMMIT();
    }
    for (int l = tid; l < NGROUP / 2; l += 128)
        ((uint32_t*)grp)[l] = ((const uint32_t*)g_gpk)[l];
    for (int l = tid; l < D * 64; l += 128) {
        int i = l >> 6, b = l & 63;
        cat[b * CAT_STRIDE + i] = g_catT[i * BATCH + b0 + b];
    }
    if (tid < 64) {   // ones column + zero pad (slots 200..207)
        float* r = cat + tid * CAT_STRIDE;
        r[200] = 1.f;
#pragma unroll
        for (int s = 201; s < 208; ++s) r[s] = 0.f;
    }

    int gid = lane >> 2;      // 0..7
    int tc  = lane & 3;       // 0..3
    int R0 = wid * 16;
    int rA = R0 + gid;
    int oa = (tc & 1) * 2;    // i offset within group
    int gsel = tc >> 1;       // which of 2 sub-groups
    // B word offsets (conflict-free via block swizzle)
    int sgB = ((gid >> 1) & 3) << 2;
    int ob[2][2];
#pragma unroll
    for (int s = 0; s < 2; ++s) {
        ob[s][0] = gid * 16 + ((s * 8 + tc) ^ sgB);
        ob[s][1] = gid * 16 + ((s * 8 + tc + 4) ^ sgB);
    }

    float acc[13][4];
#pragma unroll
    for (int t = 0; t < 13; ++t)
#pragma unroll
        for (int q = 0; q < 4; ++q) acc[t][q] = 0.f;

    __syncthreads();   // cat + grp ready

    const float* r0 = cat + rA * CAT_STRIDE;
    const float* r1 = r0 + 8 * CAT_STRIDE;

    for (int c = 0; c < NC32; ++c) {
        int s = c & 1;
        if (c + 1 < NC32) {
            const char* src = (const char*)g_SpB + (size_t)(c + 1) * SPB_CHUNK;
            uint32_t dst = sb + SP_OFF + (s ^ 1) * SPB_CHUNK;
            for (int i = tid; i < BLOAD; i += 128)
                CP_ASYNC16(dst + i * 16, src + i * 16);
            CP_COMMIT();
            asm volatile("cp.async.wait_group 1;" ::: "memory");
        } else {
            asm volatile("cp.async.wait_group 0;" ::: "memory");
        }
        __syncthreads();

        const uint32_t* spu = (const uint32_t*)(smem + SP_OFF + s * SPB_CHUNK);
        int gb = c * 8;
#pragma unroll
        for (int ks = 0; ks < 2; ++ks) {       // two k16 steps per 32-pair chunk
            int ga  = grp[gb + ks * 4 + gsel];
            int gb_ = grp[gb + ks * 4 + 2 + gsel];
            int ja = ga & 255,  ia = ga >> 8;
            int jb = gb_ & 255, ib = gb_ >> 8;
            float  ja0 = r0[ja], ja1 = r1[ja];
            float  jb0 = r0[jb], jb1 = r1[jb];
            float2 ia0 = *(const float2*)&r0[ia + oa];
            float2 ia1 = *(const float2*)&r1[ia + oa];
            float2 ib0 = *(const float2*)&r0[ib + oa];
            float2 ib1 = *(const float2*)&r1[ib + oa];
            uint32_t afr[4];
            afr[0] = pack_h2(ia0.x * ja0, ia0.y * ja0);
            afr[1] = pack_h2(ia1.x * ja1, ia1.y * ja1);
            afr[2] = pack_h2(ib0.x * jb0, ib0.y * jb0);
            afr[3] = pack_h2(ib1.x * jb1, ib1.y * jb1);
            int o0 = ob[ks][0], o1 = ob[ks][1];
#pragma unroll
            for (int t = 0; t < 13; ++t) {
                uint32_t bb0 = spu[o0 + t * 128];
                uint32_t bb1 = spu[o1 + t * 128];
                mma_f16(acc[t], afr, bb0, bb1);
            }
        }
        __syncthreads();
    }

    // epilogue: write term1 (cols < 100)
    int cb = 2 * tc;
    int r = b0 + R0 + gid;
#pragma unroll
    for (int t = 0; t < 13; ++t) {
        int n0 = cb + t * 8;
        if (n0 < NK) {
            *(float2*)&g_term1[(size_t)r * NK + n0] =
                make_float2(acc[t][0], acc[t][1]);
            *(float2*)&g_term1[(size_t)(r + 8) * NK + n0] =
                make_float2(acc[t][2], acc[t][3]);
        }
    }
}

// ---------------- hidden: h = lrelu(lrelu(term1) @ l1W^T + b), tf32 mma ----------------
#define HA_STR 108
#define HB_STR 136
#define HB_OFF 55296
#define SMEM_HID (HB_OFF + 104 * HB_STR * 4)

__global__ void __launch_bounds__(256) k_hid(const float* __restrict__ l1_b) {
    extern __shared__ char sm2[];
    float*    As = (float*)sm2;
    uint32_t* Bs = (uint32_t*)(sm2 + HB_OFF);
    int tid = threadIdx.x, lane = tid & 31, wid = tid >> 5;
    int b0 = blockIdx.x * 128, m0 = blockIdx.y * 128;

    for (int i = tid; i < 3328; i += 256) {
        int r = i >> 5, q = i & 31;
        CP_ASYNC16(smem_u32(&Bs[r * HB_STR + q * 4]),
                   (const char*)(g_l1WT + r * H1 + m0 + q * 4));
    }
    CP_COMMIT();

    {
        int r = tid >> 1, hf = tid & 1;
        const float* src = g_term1 + (size_t)(b0 + r) * NK;
        float* dst = As + r * HA_STR;
#pragma unroll 4
        for (int q = 0; q < 52; ++q) {
            int cc = hf * 52 + q;
            float v = (cc < NK) ? lrelu(src[cc]) : 0.f;
            dst[cc] = __uint_as_float(f2tf32(v));
        }
    }
    asm volatile("cp.async.wait_group 0;" ::: "memory");
    __syncthreads();

    int rw = wid & 3, cw = wid >> 2;
    int R0 = rw * 32;
    int ic = lane & 3;

    float acc[2][8][4];
#pragma unroll
    for (int f = 0; f < 2; ++f)
#pragma unroll
        for (int t = 0; t < 8; ++t)
#pragma unroll
            for (int q = 0; q < 4; ++q) acc[f][t][q] = 0.f;

#pragma unroll
    for (int kk = 0; kk < 13; ++kk) {
        uint32_t af[2][4];
#pragma unroll
        for (int f = 0; f < 2; ++f) {
            const uint32_t* hp = (const uint32_t*)As +
                (R0 + f * 16 + (lane >> 2)) * HA_STR + kk * 8 + ic;
            af[f][0] = hp[0];
            af[f][1] = hp[8 * HA_STR];
            af[f][2] = hp[4];
            af[f][3] = hp[8 * HA_STR + 4];
        }
        const uint32_t* wp = &Bs[(kk * 8 + ic) * HB_STR + cw * 64 + (lane >> 2)];
#pragma unroll
        for (int t = 0; t < 8; ++t) {
            uint32_t bb0 = wp[t * 8];
            uint32_t bb1 = wp[4 * HB_STR + t * 8];
            mma_tf32(acc[0][t], af[0], bb0, bb1);
            mma_tf32(acc[1][t], af[1], bb0, bb1);
        }
    }

#pragma unroll
    for (int t = 0; t < 8; ++t) {
        int m = m0 + cw * 64 + t * 8 + 2 * ic;
        float bm0 = l1_b[m], bm1 = l1_b[m + 1];
#pragma unroll
        for (int f = 0; f < 2; ++f) {
            int r = b0 + R0 + f * 16 + (lane >> 2);
            g_hu[(size_t)r * 256 + (m >> 1)] =
                pack_h2(lrelu(acc[f][t][0] + bm0), lrelu(acc[f][t][1] + bm1));
            g_hu[(size_t)(r + 8) * 256 + (m >> 1)] =
                pack_h2(lrelu(acc[f][t][2] + bm0), lrelu(acc[f][t][3] + bm1));
        }
    }
}

// ---------------- l2 GEMM via mma.sync fp16 ----------------
#define L2_STR 12   // words per row (8 used + 4 pad)
__global__ void __launch_bounds__(256) k_l2_mma(const float* __restrict__ l2_b,
                                                float* __restrict__ out) {
    __shared__ uint32_t hs[2][128 * L2_STR];
    __shared__ uint32_t ws[2][128 * L2_STR];
    int tid = threadIdx.x, lane = tid & 31, wid = tid >> 5;
    int b0 = blockIdx.x * 128, e0 = blockIdx.y * 128;
    int rw = wid & 3, cw = wid >> 2;
    int R0 = rw * 32;
    int gid = lane >> 2, tc = lane & 3;

    float acc[2][8][4];
#pragma unroll
    for (int f = 0; f < 2; ++f)
#pragma unroll
        for (int t = 0; t < 8; ++t)
#pragma unroll
            for (int q = 0; q < 4; ++q) acc[f][t][q] = 0.f;

    auto issue = [&](int kt, int s) {
        {
            int r = tid >> 1, q = tid & 1;
            const char* src = (const char*)(g_hu + (size_t)(b0 + r) * 256 + kt * 8) + q * 16;
            CP_ASYNC16(smem_u32(&hs[s][r * L2_STR]) + q * 16, src);
        }
        {
            int r = tid >> 1, q = tid & 1;
            const char* src = (const char*)g_l2Wh + ((size_t)(e0 + r) * 512 + kt * 16) * 2 + q * 16;
            CP_ASYNC16(smem_u32(&ws[s][r * L2_STR]) + q * 16, src);
        }
        CP_COMMIT();
    };
    issue(0, 0);

    for (int kt = 0; kt < 32; ++kt) {
        int s = kt & 1;
        if (kt + 1 < 32) {
            issue(kt + 1, s ^ 1);
            asm volatile("cp.async.wait_group 1;" ::: "memory");
        } else {
            asm volatile("cp.async.wait_group 0;" ::: "memory");
        }
        __syncthreads();

        uint32_t af[2][4];
#pragma unroll
        for (int f = 0; f < 2; ++f) {
            const uint32_t* hp = &hs[s][(R0 + f * 16 + gid) * L2_STR];
            af[f][0] = hp[tc];
            af[f][1] = hp[8 * L2_STR + tc];
            af[f][2] = hp[tc + 4];
            af[f][3] = hp[8 * L2_STR + tc + 4];
        }
        const uint32_t* wp = &ws[s][(cw * 64 + gid) * L2_STR];
#pragma unroll
        for (int t = 0; t < 8; ++t) {
            uint32_t bb0 = wp[t * 8 * L2_STR + tc];
            uint32_t bb1 = wp[t * 8 * L2_STR + tc + 4];
            mma_f16(acc[0][t], af[0], bb0, bb1);
            mma_f16(acc[1][t], af[1], bb0, bb1);
        }
        __syncthreads();
    }

#pragma unroll
    for (int t = 0; t < 8; ++t) {
        int e = e0 + cw * 64 + t * 8 + 2 * tc;
        float be0 = l2_b[e], be1 = l2_b[e + 1];
#pragma unroll
        for (int f = 0; f < 2; ++f) {
            int r = b0 + R0 + f * 16 + gid;
            *(float2*)&out[(size_t)r * EM + e] =
                make_float2(acc[f][t][0] + be0, acc[f][t][1] + be1);
            *(float2*)&out[(size_t)(r + 8) * EM + e] =
                make_float2(acc[f][t][2] + be0, acc[f][t][3] + be1);
        }
    }
}

// ---------------- row-wise L2 normalization ----------------
__global__ void __launch_bounds__(256) k_norm(float* __restrict__ out) {
    __shared__ float wsum[8];
    int b = blockIdx.x;
    int t = threadIdx.x;
    float4* row = (float4*)(out + (size_t)b * EM);
    float4 v = row[t];
    float s = v.x * v.x + v.y * v.y + v.z * v.z + v.w * v.w;
#pragma unroll
    for (int off = 16; off > 0; off >>= 1)
        s += __shfl_xor_sync(0xffffffffu, s, off);
    if ((t & 31) == 0) wsum[t >> 5] = s;
    __syncthreads();
    float tot = wsum[0] + wsum[1] + wsum[2] + wsum[3] +
                wsum[4] + wsum[5] + wsum[6] + wsum[7];
    float inv = rsqrtf(tot);
    row[t] = make_float4(v.x * inv, v.y * inv, v.z * inv, v.w * inv);
}

// ---------------- launch ----------------
extern "C" void kernel_launch(void* const* d_in, const int* in_sizes, int n_in,
                              void* d_out, int out_size) {
    const int*   x       = (const int*)d_in[0];
    const float* embed_W = (const float*)d_in[2];
    const float* pd_W    = (const float*)d_in[3];
    const float* pd_b    = (const float*)d_in[4];
    const float* comp_T  = (const float*)d_in[5];
    const float* cl_W    = (const float*)d_in[6];
    const float* cl_b    = (const float*)d_in[7];
    const float* l1_W    = (const float*)d_in[8];
    const float* l1_b    = (const float*)d_in[9];
    const float* l2_W    = (const float*)d_in[10];
    const float* l2_b    = (const float*)d_in[11];
    float* out = (float*)d_out;

    k_prep_groups<<<1, 256>>>();
    k_prep_small<<<128, 256>>>(pd_W, l1_W);
    k_prep_spb<<<NC32, 256>>>(comp_T, cl_W, cl_b);
    k_prep_l2h<<<(H1 * EM) / 256, 256>>>(l2_W);
    k_cat<<<(2 * BATCH) / 16, 256>>>(x, embed_W, pd_b);

    cudaFuncSetAttribute(k_main_mma, cudaFuncAttributeMaxDynamicSharedMemorySize,
                         SMEM_MAIN);
    k_main_mma<<<BATCH / 64, 128, SMEM_MAIN>>>();

    cudaFuncSetAttribute(k_hid, cudaFuncAttributeMaxDynamicSharedMemorySize,
                         SMEM_HID);
    k_hid<<<dim3(BATCH / 128, 4), 256, SMEM_HID>>>(l1_b);

    k_l2_mma<<<dim3(BATCH / 128, EM / 128), 256>>>(l2_b, out);
    k_norm<<<BATCH, 256>>>(out);
}